// round 6
// baseline (speedup 1.0000x reference)
#include <cuda_runtime.h>
#include <cuda_bf16.h>
#include <math.h>
#include <stdint.h>

#define BATCH 8
#define SEQ   1024
#define DMODEL 1024
#define NHEADS 16
#define DK    64
#define NREL  257
#define MAXREL 128
#define MTOT  (BATCH*SEQ)
#define BH    (BATCH*NHEADS)

__device__ float g_Q[BH*SEQ*DK];
__device__ float g_K[BH*SEQ*DK];
__device__ float g_V[BH*SEQ*DK];
__device__ float g_Qrel[BH*SEQ*NREL];
__device__ float g_ctx[MTOT*DMODEL];
__device__ __nv_bfloat16 g_Ah[MTOT*DMODEL];
__device__ __nv_bfloat16 g_Al[MTOT*DMODEL];
__device__ __nv_bfloat16 g_Wh[DMODEL*DMODEL];
__device__ __nv_bfloat16 g_Wl[DMODEL*DMODEL];

// ---------------- helpers ----------------
__device__ __forceinline__ uint32_t s2u(const void* p) {
    uint32_t a;
    asm("{ .reg .u64 t; cvta.to.shared.u64 t, %1; cvt.u32.u64 %0, t; }" : "=r"(a) : "l"(p));
    return a;
}
__device__ __forceinline__ void cp16(uint32_t dst, const void* src) {
    asm volatile("cp.async.cg.shared.global [%0], [%1], 16;" :: "r"(dst), "l"(src) : "memory");
}
__device__ __forceinline__ void ldm4(uint32_t* r, uint32_t addr) {
    asm volatile("ldmatrix.sync.aligned.m8n8.x4.shared.b16 {%0,%1,%2,%3}, [%4];"
                 : "=r"(r[0]), "=r"(r[1]), "=r"(r[2]), "=r"(r[3]) : "r"(addr));
}
__device__ __forceinline__ void mma16816(float* d, const uint32_t* a, const uint32_t* b) {
    asm volatile(
        "mma.sync.aligned.m16n8k16.row.col.f32.bf16.bf16.f32 "
        "{%0,%1,%2,%3}, {%4,%5,%6,%7}, {%8,%9}, {%0,%1,%2,%3};"
        : "+f"(d[0]), "+f"(d[1]), "+f"(d[2]), "+f"(d[3])
        : "r"(a[0]), "r"(a[1]), "r"(a[2]), "r"(a[3]), "r"(b[0]), "r"(b[1]));
}

// ---------------- fp32 -> bf16 hi/lo split ----------------
__global__ __launch_bounds__(256) void cvt_split(const float4* __restrict__ x,
                                                 uint2* __restrict__ hi,
                                                 uint2* __restrict__ lo) {
    const int i = blockIdx.x * 256 + threadIdx.x;
    const float4 v = x[i];
    __nv_bfloat16 h0 = __float2bfloat16(v.x), h1 = __float2bfloat16(v.y);
    __nv_bfloat16 h2 = __float2bfloat16(v.z), h3 = __float2bfloat16(v.w);
    __nv_bfloat16 l0 = __float2bfloat16(v.x - __bfloat162float(h0));
    __nv_bfloat16 l1 = __float2bfloat16(v.y - __bfloat162float(h1));
    __nv_bfloat16 l2 = __float2bfloat16(v.z - __bfloat162float(h2));
    __nv_bfloat16 l3 = __float2bfloat16(v.w - __bfloat16_as_ushort(h3) * 0.f - __bfloat162float(h3));
    uint2 H, L;
    H.x = (uint32_t)__bfloat16_as_ushort(h0) | ((uint32_t)__bfloat16_as_ushort(h1) << 16);
    H.y = (uint32_t)__bfloat16_as_ushort(h2) | ((uint32_t)__bfloat16_as_ushort(h3) << 16);
    L.x = (uint32_t)__bfloat16_as_ushort(l0) | ((uint32_t)__bfloat16_as_ushort(l1) << 16);
    L.y = (uint32_t)__bfloat16_as_ushort(l2) | ((uint32_t)__bfloat16_as_ushort(l3) << 16);
    hi[i] = H;
    lo[i] = L;
}

// ---------------- mma.sync bf16 split GEMM (unchanged from R5) ----------------
#define PITCH 72
#define MATB (128*PITCH*2)
#define STAGEB (4*MATB)
#define GEMM_SMEM (2*STAGEB)

template<int MODE>
__global__ __launch_bounds__(256, 1) void gemm_mma(const __nv_bfloat16* __restrict__ Ah,
                                                   const __nv_bfloat16* __restrict__ Al,
                                                   const __nv_bfloat16* __restrict__ Wh,
                                                   const __nv_bfloat16* __restrict__ Wl,
                                                   const float* __restrict__ bias,
                                                   float* __restrict__ out) {
    extern __shared__ char smc[];
    const uint32_t sb = s2u(smc);
    const int tid = threadIdx.x, wid = tid >> 5, lane = tid & 31;
    const int m0 = blockIdx.y * 128, n0 = blockIdx.x * 128;
    const int wm = wid >> 2, wn = wid & 3;

    float acc[4][4][4];
#pragma unroll
    for (int i = 0; i < 4; i++)
#pragma unroll
        for (int j = 0; j < 4; j++)
#pragma unroll
            for (int q = 0; q < 4; q++) acc[i][j][q] = 0.f;

    auto issue = [&](int s) {
        const uint32_t bu = sb + (s & 1) * STAGEB;
        const int k0 = s * 64;
#pragma unroll
        for (int it = 0; it < 4; it++) {
            const int idx = tid + it * 256;
            const int row = idx >> 3, j = idx & 7;
            const uint32_t doff = row * (PITCH * 2) + j * 16;
            const size_t ga = ((size_t)(m0 + row) * 1024 + k0 + j * 8) * 2;
            const size_t gw = ((size_t)(n0 + row) * 1024 + k0 + j * 8) * 2;
            cp16(bu + 0 * MATB + doff, (const char*)Ah + ga);
            cp16(bu + 1 * MATB + doff, (const char*)Al + ga);
            cp16(bu + 2 * MATB + doff, (const char*)Wh + gw);
            cp16(bu + 3 * MATB + doff, (const char*)Wl + gw);
        }
        asm volatile("cp.async.commit_group;" ::: "memory");
    };

    issue(0);
    for (int s = 0; s < 16; s++) {
        if (s + 1 < 16) {
            issue(s + 1);
            asm volatile("cp.async.wait_group 1;" ::: "memory");
        } else {
            asm volatile("cp.async.wait_group 0;" ::: "memory");
        }
        __syncthreads();
        const uint32_t bu = sb + (s & 1) * STAGEB;
#pragma unroll
        for (int kk = 0; kk < 4; kk++) {
            const int k16 = kk * 16;
            uint32_t ah[4][4], al[4][4];
#pragma unroll
            for (int i = 0; i < 4; i++) {
                const uint32_t addr = bu +
                    ((wm * 64 + i * 16 + (lane & 15)) * PITCH + k16 + (lane >> 4) * 8) * 2;
                ldm4(ah[i], addr);
                ldm4(al[i], addr + MATB);
            }
            uint32_t wh[2][4], wl[2][4];
#pragma unroll
            for (int j = 0; j < 2; j++) {
                const int mat = lane >> 3, rr = lane & 7;
                const int n = wn * 32 + j * 16 + (mat >> 1) * 8 + rr;
                const int k = k16 + (mat & 1) * 8;
                const uint32_t addr = bu + 2 * MATB + (n * PITCH + k) * 2;
                ldm4(wh[j], addr);
                ldm4(wl[j], addr + MATB);
            }
#pragma unroll
            for (int i = 0; i < 4; i++)
#pragma unroll
                for (int nt = 0; nt < 4; nt++) {
                    const uint32_t* bhf = &wh[nt >> 1][(nt & 1) * 2];
                    const uint32_t* blf = &wl[nt >> 1][(nt & 1) * 2];
                    mma16816(acc[i][nt], ah[i], bhf);
                    mma16816(acc[i][nt], ah[i], blf);
                    mma16816(acc[i][nt], al[i], bhf);
                }
        }
        __syncthreads();
    }

    const int rr = lane >> 2, cc = (lane & 3) * 2;
#pragma unroll
    for (int i = 0; i < 4; i++) {
#pragma unroll
        for (int nt = 0; nt < 4; nt++) {
            const int n = n0 + wn * 32 + nt * 8 + cc;
#pragma unroll
            for (int half = 0; half < 2; half++) {
                const int m = m0 + wm * 64 + i * 16 + rr + half * 8;
                float2 v;
                v.x = acc[i][nt][half * 2 + 0];
                v.y = acc[i][nt][half * 2 + 1];
                if (MODE == 0) {
                    const int b = m >> 10, sI = m & 1023, h = n >> 6, dd = n & 63;
                    *(float2*)(out + (((size_t)(b * NHEADS + h) << 10) + sI) * 64 + dd) = v;
                } else {
                    v.x += bias[n];
                    v.y += bias[n + 1];
                    *(float2*)(out + (size_t)m * 1024 + n) = v;
                }
            }
        }
    }
}

// ---------------- Qrel: float4 inner loop ----------------
#define QP 68
__global__ __launch_bounds__(256) void qrel_kernel(const float* __restrict__ Qg,
                                                   const float* __restrict__ relk,
                                                   float* __restrict__ Qrel) {
    __shared__ float Qs[64 * QP];
    __shared__ float Rs[64 * QP];
    const int tid = threadIdx.x;
    const int p0 = blockIdx.x * 64, l0 = blockIdx.y * 64, bh = blockIdx.z;
#pragma unroll
    for (int i = 0; i < 16; i++) {
        const int lin = tid + i * 256;
        const int row = lin >> 6, col = lin & 63;
        Qs[row * QP + col] = Qg[((size_t)((bh << 10) + l0 + row)) * DK + col];
        const int p = p0 + row;
        Rs[row * QP + col] = (p < NREL) ? relk[p * DK + col] : 0.f;
    }
    __syncthreads();
    const int tx = tid & 15, ty = tid >> 4;
    float acc[4][4];
#pragma unroll
    for (int i = 0; i < 4; i++)
#pragma unroll
        for (int j = 0; j < 4; j++) acc[i][j] = 0.f;
#pragma unroll
    for (int k4 = 0; k4 < 16; k4++) {
        float4 q[4], rv[4];
#pragma unroll
        for (int i = 0; i < 4; i++)
            q[i] = *(const float4*)(Qs + (ty * 4 + i) * QP + k4 * 4);
#pragma unroll
        for (int j = 0; j < 4; j++)
            rv[j] = *(const float4*)(Rs + (tx * 4 + j) * QP + k4 * 4);
#pragma unroll
        for (int i = 0; i < 4; i++)
#pragma unroll
            for (int j = 0; j < 4; j++)
                acc[i][j] += q[i].x * rv[j].x + q[i].y * rv[j].y
                           + q[i].z * rv[j].z + q[i].w * rv[j].w;
    }
#pragma unroll
    for (int i = 0; i < 4; i++) {
        const int l = l0 + ty * 4 + i;
#pragma unroll
        for (int j = 0; j < 4; j++) {
            const int p = p0 + tx * 4 + j;
            if (p < NREL)
                Qrel[((size_t)((bh << 10) + l)) * NREL + p] = acc[i][j];
        }
    }
}

// ---------------- attn (unchanged from R5) ----------------
#define ATTN_SMEM_FLOATS (16*1024 + 16*64 + 256 + 16 + 16)
__global__ __launch_bounds__(256) void attn_kernel(const float* __restrict__ Qg,
                                                   const float* __restrict__ Kg,
                                                   const float* __restrict__ Qrel,
                                                   const float* __restrict__ decay,
                                                   float* __restrict__ attn) {
    extern __shared__ float sm[];
    float* sbuf = sm;
    float* Qs   = sm + 16 * 1024;
    float* red  = Qs + 16 * 64;
    float* rowm = red + 256;
    float* rows = rowm + 16;

    const int tid = threadIdx.x;
    const int bh = blockIdx.y;
    const int h  = bh & 15;
    const int l0 = blockIdx.x * 16;
    const float dh = decay[h];

#pragma unroll
    for (int i = 0; i < 4; i++) {
        const int lin = tid + i * 256;
        Qs[lin] = Qg[((size_t)((bh << 10) + l0 + (lin >> 6))) * DK + (lin & 63)];
    }
    __syncthreads();
    const float4* Qs4 = (const float4*)Qs;

    for (int ch = 0; ch < 4; ch++) {
        const int r = (ch << 8) + tid;
        float4 kr[16];
        const float4* kp = (const float4*)(Kg + (((size_t)(bh << 10)) + r) * 64);
#pragma unroll
        for (int i = 0; i < 16; i++) kr[i] = kp[i];
        float acc[16];
#pragma unroll
        for (int i = 0; i < 16; i++) acc[i] = 0.f;
#pragma unroll
        for (int k4 = 0; k4 < 16; k4++) {
            const float4 kv = kr[k4];
#pragma unroll
            for (int row = 0; row < 16; row++) {
                const float4 q = Qs4[row * 16 + k4];
                acc[row] = fmaf(q.x, kv.x, fmaf(q.y, kv.y,
                           fmaf(q.z, kv.z, fmaf(q.w, kv.w, acc[row]))));
            }
        }
#pragma unroll
        for (int row = 0; row < 16; row++) {
            const int lg = l0 + row;
            const int rel = r - lg;
            const int relc = rel < -MAXREL ? -MAXREL : (rel > MAXREL ? MAXREL : rel);
            const float sc = acc[row] * 0.125f
                           + __ldg(Qrel + ((size_t)((bh << 10) + lg)) * NREL + relc + MAXREL)
                           - dh * fabsf((float)rel);
            sbuf[(row << 10) + r] = sc;
        }
    }
    __syncthreads();

    const int row = tid >> 4, lane = tid & 15;
    float m = -3.0e38f;
    for (int j = 0; j < 64; j++) m = fmaxf(m, sbuf[(row << 10) + lane + (j << 4)]);
    red[row * 16 + lane] = m;
    __syncthreads();
    if (lane == 0) {
        float mm = red[row * 16];
        for (int j = 1; j < 16; j++) mm = fmaxf(mm, red[row * 16 + j]);
        rowm[row] = mm;
    }
    __syncthreads();
    const float mm = rowm[row];
    float sum = 0.f;
    for (int j = 0; j < 64; j++) {
        const int c = lane + (j << 4);
        const float e = __expf(sbuf[(row << 10) + c] - mm);
        sbuf[(row << 10) + c] = e;
        sum += e;
    }
    red[row * 16 + lane] = sum;
    __syncthreads();
    if (lane == 0) {
        float ss = 0.f;
        for (int j = 0; j < 16; j++) ss += red[row * 16 + j];
        rows[row] = ss;
    }
    __syncthreads();

    for (int l = 0; l < 16; l++) {
        const float inv = 1.0f / rows[l];
        float* dst = attn + (((size_t)(bh << 10) + l0 + l) << 10);
#pragma unroll
        for (int j = 0; j < 4; j++) {
            const int c = tid + (j << 8);
            dst[c] = sbuf[(l << 10) + c] * inv;
        }
    }
}

// ---------------- ctx: float4 transposed-V rewrite ----------------
#define VP 76                          // Vt/At pitch (floats), 16B aligned
#define AGP 260                        // aggs pitch (floats), 16B aligned
__global__ __launch_bounds__(256) void ctx_kernel(const float* __restrict__ attn,
                                                  const float* __restrict__ Vg,
                                                  const float* __restrict__ relv,
                                                  float* __restrict__ ctx) {
    __shared__ float At[16 * VP];
    __shared__ float Vt[64 * VP];      // Vt[d][rr] transposed
    __shared__ float aggs[16 * AGP];

    const int tid = threadIdx.x;
    const int bh = blockIdx.y, b = bh >> 4, h = bh & 15;
    const int l0 = blockIdx.x * 16;

    for (int i = tid; i < 16 * AGP; i += 256) aggs[i] = 0.f;
    __syncthreads();

    const int d = tid & 63, lg4 = tid >> 6;
    const int row = tid >> 4, lane = tid & 15;
    float acc[4] = {0.f, 0.f, 0.f, 0.f};
    float c0 = 0.f, c1 = 0.f;

    for (int rc = 0; rc < 16; rc++) {
#pragma unroll
        for (int i = 0; i < 4; i++) {
            const int lin = tid + i * 256;
            const int ar = lin >> 6, ac = lin & 63;
            At[ar * VP + ac] = attn[(((size_t)(bh << 10) + l0 + ar) << 10) + (rc << 6) + ac];
        }
#pragma unroll
        for (int i = 0; i < 16; i++) {
            const int lin = tid + i * 256;
            const int vr = lin >> 6, vc = lin & 63;
            Vt[vc * VP + vr] = Vg[((size_t)((bh << 10) + (rc << 6) + vr)) * DK + vc];
        }
        __syncthreads();
        {
            const float4* V4 = (const float4*)(Vt + d * VP);
            const float4* A0 = (const float4*)(At + lg4 * VP);
            const float4* A1 = (const float4*)(At + (lg4 + 4) * VP);
            const float4* A2 = (const float4*)(At + (lg4 + 8) * VP);
            const float4* A3 = (const float4*)(At + (lg4 + 12) * VP);
#pragma unroll
            for (int q = 0; q < 16; q++) {
                const float4 vv = V4[q];
                float4 a;
                a = A0[q]; acc[0] += a.x * vv.x + a.y * vv.y + a.z * vv.z + a.w * vv.w;
                a = A1[q]; acc[1] += a.x * vv.x + a.y * vv.y + a.z * vv.z + a.w * vv.w;
                a = A2[q]; acc[2] += a.x * vv.x + a.y * vv.y + a.z * vv.z + a.w * vv.w;
                a = A3[q]; acc[3] += a.x * vv.x + a.y * vv.y + a.z * vv.z + a.w * vv.w;
            }
        }
#pragma unroll
        for (int jj = 0; jj < 4; jj++) {
            const int rr = lane + (jj << 4);
            const int r = (rc << 6) + rr;
            const float a = At[row * VP + rr];
            const int rel = r - (l0 + row);
            if (rel <= -MAXREL)      c0 += a;
            else if (rel >= MAXREL)  c1 += a;
            else                     aggs[row * AGP + rel + MAXREL] = a;  // unique writer
        }
        __syncthreads();
    }
    atomicAdd(&aggs[row * AGP + 0], c0);
    atomicAdd(&aggs[row * AGP + 256], c1);
    __syncthreads();

    // agg @ rel_v: 4 chunks of 64 buckets + scalar tail p=256
    for (int p0 = 0; p0 < 256; p0 += 64) {
#pragma unroll
        for (int i = 0; i < 16; i++) {
            const int lin = tid + i * 256;
            const int vr = lin >> 6, vc = lin & 63;
            Vt[vc * VP + vr] = relv[(p0 + vr) * DK + vc];
        }
        __syncthreads();
        {
            const float4* V4 = (const float4*)(Vt + d * VP);
            const float4* G0 = (const float4*)(aggs + lg4 * AGP + p0);
            const float4* G1 = (const float4*)(aggs + (lg4 + 4) * AGP + p0);
            const float4* G2 = (const float4*)(aggs + (lg4 + 8) * AGP + p0);
            const float4* G3 = (const float4*)(aggs + (lg4 + 12) * AGP + p0);
#pragma unroll
            for (int q = 0; q < 16; q++) {
                const float4 vv = V4[q];
                float4 a;
                a = G0[q]; acc[0] += a.x * vv.x + a.y * vv.y + a.z * vv.z + a.w * vv.w;
                a = G1[q]; acc[1] += a.x * vv.x + a.y * vv.y + a.z * vv.z + a.w * vv.w;
                a = G2[q]; acc[2] += a.x * vv.x + a.y * vv.y + a.z * vv.z + a.w * vv.w;
                a = G3[q]; acc[3] += a.x * vv.x + a.y * vv.y + a.z * vv.z + a.w * vv.w;
            }
        }
        __syncthreads();
    }
    {
        const float rv = relv[256 * DK + d];
        acc[0] += aggs[lg4 * AGP + 256] * rv;
        acc[1] += aggs[(lg4 + 4) * AGP + 256] * rv;
        acc[2] += aggs[(lg4 + 8) * AGP + 256] * rv;
        acc[3] += aggs[(lg4 + 12) * AGP + 256] * rv;
    }

#pragma unroll
    for (int i = 0; i < 4; i++) {
        const int lg = l0 + lg4 + 4 * i;
        ctx[(((size_t)(b << 10) + lg) << 10) + (h << 6) + d] = acc[i];
    }
}

// ---------------------------------------------------------------------------
extern "C" void kernel_launch(void* const* d_in, const int* in_sizes, int n_in,
                              void* d_out, int out_size) {
    const float* query = (const float*)d_in[0];
    const float* key_  = (const float*)d_in[1];
    const float* value = (const float*)d_in[2];
    const float* w_q   = (const float*)d_in[3];
    const float* w_k   = (const float*)d_in[4];
    const float* w_v   = (const float*)d_in[5];
    const float* w_o   = (const float*)d_in[6];
    const float* b_o   = (const float*)d_in[7];
    const float* rel_k = (const float*)d_in[8];
    const float* rel_v = (const float*)d_in[9];
    const float* decay = (const float*)d_in[10];

    float* out  = (float*)d_out;
    float* attn = out + (size_t)MTOT * DMODEL;

    float *Q, *K, *V, *Qrel, *ctx;
    __nv_bfloat16 *Ah, *Al, *Wh, *Wl;
    cudaGetSymbolAddress((void**)&Q,    g_Q);
    cudaGetSymbolAddress((void**)&K,    g_K);
    cudaGetSymbolAddress((void**)&V,    g_V);
    cudaGetSymbolAddress((void**)&Qrel, g_Qrel);
    cudaGetSymbolAddress((void**)&ctx,  g_ctx);
    cudaGetSymbolAddress((void**)&Ah,   g_Ah);
    cudaGetSymbolAddress((void**)&Al,   g_Al);
    cudaGetSymbolAddress((void**)&Wh,   g_Wh);
    cudaGetSymbolAddress((void**)&Wl,   g_Wl);

    cudaFuncSetAttribute(gemm_mma<0>, cudaFuncAttributeMaxDynamicSharedMemorySize, GEMM_SMEM);
    cudaFuncSetAttribute(gemm_mma<1>, cudaFuncAttributeMaxDynamicSharedMemorySize, GEMM_SMEM);

    const int nA4 = MTOT * DMODEL / 4;
    const int nW4 = DMODEL * DMODEL / 4;
    const dim3 ggemm(DMODEL / 128, MTOT / 128);

    cvt_split<<<nA4 / 256, 256>>>((const float4*)query, (uint2*)Ah, (uint2*)Al);
    cvt_split<<<nW4 / 256, 256>>>((const float4*)w_q, (uint2*)Wh, (uint2*)Wl);
    gemm_mma<0><<<ggemm, 256, GEMM_SMEM>>>(Ah, Al, Wh, Wl, nullptr, Q);

    cvt_split<<<nA4 / 256, 256>>>((const float4*)key_, (uint2*)Ah, (uint2*)Al);
    cvt_split<<<nW4 / 256, 256>>>((const float4*)w_k, (uint2*)Wh, (uint2*)Wl);
    gemm_mma<0><<<ggemm, 256, GEMM_SMEM>>>(Ah, Al, Wh, Wl, nullptr, K);

    cvt_split<<<nA4 / 256, 256>>>((const float4*)value, (uint2*)Ah, (uint2*)Al);
    cvt_split<<<nW4 / 256, 256>>>((const float4*)w_v, (uint2*)Wh, (uint2*)Wl);
    gemm_mma<0><<<ggemm, 256, GEMM_SMEM>>>(Ah, Al, Wh, Wl, nullptr, V);

    qrel_kernel<<<dim3(5, 16, BH), 256>>>(Q, rel_k, Qrel);

    static const size_t attn_smem = ATTN_SMEM_FLOATS * sizeof(float);
    cudaFuncSetAttribute(attn_kernel, cudaFuncAttributeMaxDynamicSharedMemorySize,
                         (int)attn_smem);
    attn_kernel<<<dim3(SEQ / 16, BH), 256, attn_smem>>>(Q, K, Qrel, decay, attn);

    ctx_kernel<<<dim3(SEQ / 16, BH), 256>>>(attn, V, rel_v, ctx);

    cvt_split<<<nA4 / 256, 256>>>((const float4*)ctx, (uint2*)Ah, (uint2*)Al);
    cvt_split<<<nW4 / 256, 256>>>((const float4*)w_o, (uint2*)Wh, (uint2*)Wl);
    gemm_mma<1><<<ggemm, 256, GEMM_SMEM>>>(Ah, Al, Wh, Wl, b_o, out);
}

// round 7
// speedup vs baseline: 1.2040x; 1.2040x over previous
#include <cuda_runtime.h>
#include <cuda_bf16.h>
#include <math.h>
#include <stdint.h>

#define BATCH 8
#define SEQ   1024
#define DMODEL 1024
#define NHEADS 16
#define DK    64
#define NREL  257
#define MAXREL 128
#define MTOT  (BATCH*SEQ)
#define BH    (BATCH*NHEADS)

__device__ float g_Q[BH*SEQ*DK];
__device__ float g_K[BH*SEQ*DK];
__device__ float g_V[BH*SEQ*DK];
__device__ float g_Qrel[BH*SEQ*NREL];
__device__ float g_ctx[MTOT*DMODEL];
__device__ __nv_bfloat16 g_Ah[MTOT*DMODEL];
__device__ __nv_bfloat16 g_Al[MTOT*DMODEL];
__device__ __nv_bfloat16 g_Wh[DMODEL*DMODEL];
__device__ __nv_bfloat16 g_Wl[DMODEL*DMODEL];
__device__ __nv_bfloat16 g_Qh[BH*SEQ*DK];
__device__ __nv_bfloat16 g_Ql[BH*SEQ*DK];
__device__ __nv_bfloat16 g_Kh[BH*SEQ*DK];
__device__ __nv_bfloat16 g_Kl[BH*SEQ*DK];
__device__ __nv_bfloat16 g_Vh[BH*SEQ*DK];
__device__ __nv_bfloat16 g_Vl[BH*SEQ*DK];

// ---------------- helpers ----------------
__device__ __forceinline__ uint32_t s2u(const void* p) {
    uint32_t a;
    asm("{ .reg .u64 t; cvta.to.shared.u64 t, %1; cvt.u32.u64 %0, t; }" : "=r"(a) : "l"(p));
    return a;
}
__device__ __forceinline__ void cp16(uint32_t dst, const void* src) {
    asm volatile("cp.async.cg.shared.global [%0], [%1], 16;" :: "r"(dst), "l"(src) : "memory");
}
__device__ __forceinline__ void ldm4(uint32_t* r, uint32_t addr) {
    asm volatile("ldmatrix.sync.aligned.m8n8.x4.shared.b16 {%0,%1,%2,%3}, [%4];"
                 : "=r"(r[0]), "=r"(r[1]), "=r"(r[2]), "=r"(r[3]) : "r"(addr));
}
__device__ __forceinline__ void mma16816(float* d, const uint32_t* a, const uint32_t* b) {
    asm volatile(
        "mma.sync.aligned.m16n8k16.row.col.f32.bf16.bf16.f32 "
        "{%0,%1,%2,%3}, {%4,%5,%6,%7}, {%8,%9}, {%0,%1,%2,%3};"
        : "+f"(d[0]), "+f"(d[1]), "+f"(d[2]), "+f"(d[3])
        : "r"(a[0]), "r"(a[1]), "r"(a[2]), "r"(a[3]), "r"(b[0]), "r"(b[1]));
}

// ---------------- fp32 -> bf16 hi/lo split ----------------
__global__ __launch_bounds__(256) void cvt_split(const float4* __restrict__ x,
                                                 uint2* __restrict__ hi,
                                                 uint2* __restrict__ lo) {
    const int i = blockIdx.x * 256 + threadIdx.x;
    const float4 v = x[i];
    __nv_bfloat16 h0 = __float2bfloat16(v.x), h1 = __float2bfloat16(v.y);
    __nv_bfloat16 h2 = __float2bfloat16(v.z), h3 = __float2bfloat16(v.w);
    __nv_bfloat16 l0 = __float2bfloat16(v.x - __bfloat162float(h0));
    __nv_bfloat16 l1 = __float2bfloat16(v.y - __bfloat162float(h1));
    __nv_bfloat16 l2 = __float2bfloat16(v.z - __bfloat162float(h2));
    __nv_bfloat16 l3 = __float2bfloat16(v.w - __bfloat162float(h3));
    uint2 H, L;
    H.x = (uint32_t)__bfloat16_as_ushort(h0) | ((uint32_t)__bfloat16_as_ushort(h1) << 16);
    H.y = (uint32_t)__bfloat16_as_ushort(h2) | ((uint32_t)__bfloat16_as_ushort(h3) << 16);
    L.x = (uint32_t)__bfloat16_as_ushort(l0) | ((uint32_t)__bfloat16_as_ushort(l1) << 16);
    L.y = (uint32_t)__bfloat16_as_ushort(l2) | ((uint32_t)__bfloat16_as_ushort(l3) << 16);
    hi[i] = H;
    lo[i] = L;
}

// ---------------- mma.sync bf16 split GEMM ----------------
// MODE 0: projection layout [B,H,S,dk] fp32 + bf16 hi/lo splits; MODE 1: row-major + bias
#define PITCH 72
#define MATB (128*PITCH*2)
#define STAGEB (4*MATB)
#define GEMM_SMEM (2*STAGEB)

template<int MODE>
__global__ __launch_bounds__(256, 1) void gemm_mma(const __nv_bfloat16* __restrict__ Ah,
                                                   const __nv_bfloat16* __restrict__ Al,
                                                   const __nv_bfloat16* __restrict__ Wh,
                                                   const __nv_bfloat16* __restrict__ Wl,
                                                   const float* __restrict__ bias,
                                                   float* __restrict__ out,
                                                   __nv_bfloat16* __restrict__ sh,
                                                   __nv_bfloat16* __restrict__ sl) {
    extern __shared__ char smc[];
    const uint32_t sb = s2u(smc);
    const int tid = threadIdx.x, wid = tid >> 5, lane = tid & 31;
    const int m0 = blockIdx.y * 128, n0 = blockIdx.x * 128;
    const int wm = wid >> 2, wn = wid & 3;

    float acc[4][4][4];
#pragma unroll
    for (int i = 0; i < 4; i++)
#pragma unroll
        for (int j = 0; j < 4; j++)
#pragma unroll
            for (int q = 0; q < 4; q++) acc[i][j][q] = 0.f;

    auto issue = [&](int s) {
        const uint32_t bu = sb + (s & 1) * STAGEB;
        const int k0 = s * 64;
#pragma unroll
        for (int it = 0; it < 4; it++) {
            const int idx = tid + it * 256;
            const int row = idx >> 3, j = idx & 7;
            const uint32_t doff = row * (PITCH * 2) + j * 16;
            const size_t ga = ((size_t)(m0 + row) * 1024 + k0 + j * 8) * 2;
            const size_t gw = ((size_t)(n0 + row) * 1024 + k0 + j * 8) * 2;
            cp16(bu + 0 * MATB + doff, (const char*)Ah + ga);
            cp16(bu + 1 * MATB + doff, (const char*)Al + ga);
            cp16(bu + 2 * MATB + doff, (const char*)Wh + gw);
            cp16(bu + 3 * MATB + doff, (const char*)Wl + gw);
        }
        asm volatile("cp.async.commit_group;" ::: "memory");
    };

    issue(0);
    for (int s = 0; s < 16; s++) {
        if (s + 1 < 16) {
            issue(s + 1);
            asm volatile("cp.async.wait_group 1;" ::: "memory");
        } else {
            asm volatile("cp.async.wait_group 0;" ::: "memory");
        }
        __syncthreads();
        const uint32_t bu = sb + (s & 1) * STAGEB;
#pragma unroll
        for (int kk = 0; kk < 4; kk++) {
            const int k16 = kk * 16;
            uint32_t ah[4][4], al[4][4];
#pragma unroll
            for (int i = 0; i < 4; i++) {
                const uint32_t addr = bu +
                    ((wm * 64 + i * 16 + (lane & 15)) * PITCH + k16 + (lane >> 4) * 8) * 2;
                ldm4(ah[i], addr);
                ldm4(al[i], addr + MATB);
            }
            uint32_t wh[2][4], wl[2][4];
#pragma unroll
            for (int j = 0; j < 2; j++) {
                const int mat = lane >> 3, rr = lane & 7;
                const int n = wn * 32 + j * 16 + (mat >> 1) * 8 + rr;
                const int k = k16 + (mat & 1) * 8;
                const uint32_t addr = bu + 2 * MATB + (n * PITCH + k) * 2;
                ldm4(wh[j], addr);
                ldm4(wl[j], addr + MATB);
            }
#pragma unroll
            for (int i = 0; i < 4; i++)
#pragma unroll
                for (int nt = 0; nt < 4; nt++) {
                    const uint32_t* bhf = &wh[nt >> 1][(nt & 1) * 2];
                    const uint32_t* blf = &wl[nt >> 1][(nt & 1) * 2];
                    mma16816(acc[i][nt], ah[i], bhf);
                    mma16816(acc[i][nt], ah[i], blf);
                    mma16816(acc[i][nt], al[i], bhf);
                }
        }
        __syncthreads();
    }

    const int rr = lane >> 2, cc = (lane & 3) * 2;
#pragma unroll
    for (int i = 0; i < 4; i++) {
#pragma unroll
        for (int nt = 0; nt < 4; nt++) {
            const int n = n0 + wn * 32 + nt * 8 + cc;
#pragma unroll
            for (int half = 0; half < 2; half++) {
                const int m = m0 + wm * 64 + i * 16 + rr + half * 8;
                float2 v;
                v.x = acc[i][nt][half * 2 + 0];
                v.y = acc[i][nt][half * 2 + 1];
                if (MODE == 0) {
                    const int b = m >> 10, sI = m & 1023, h = n >> 6, dd = n & 63;
                    const size_t off = (((size_t)(b * NHEADS + h) << 10) + sI) * 64 + dd;
                    *(float2*)(out + off) = v;
                    // bf16 hi/lo split for downstream mma use
                    __nv_bfloat16 h0 = __float2bfloat16(v.x);
                    __nv_bfloat16 h1 = __float2bfloat16(v.y);
                    __nv_bfloat16 L0 = __float2bfloat16(v.x - __bfloat162float(h0));
                    __nv_bfloat16 L1 = __float2bfloat16(v.y - __bfloat162float(h1));
                    *(uint32_t*)(sh + off) = (uint32_t)__bfloat16_as_ushort(h0)
                                           | ((uint32_t)__bfloat16_as_ushort(h1) << 16);
                    *(uint32_t*)(sl + off) = (uint32_t)__bfloat16_as_ushort(L0)
                                           | ((uint32_t)__bfloat16_as_ushort(L1) << 16);
                } else {
                    v.x += bias[n];
                    v.y += bias[n + 1];
                    *(float2*)(out + (size_t)m * 1024 + n) = v;
                }
            }
        }
    }
}

// ---------------- Qrel (R5 scalar version, 218us) ----------------
__global__ __launch_bounds__(256) void qrel_kernel(const float* __restrict__ Qg,
                                                   const float* __restrict__ relk,
                                                   float* __restrict__ Qrel) {
    __shared__ float Qs[64][65];
    __shared__ float Rs[64][65];
    const int tid = threadIdx.x;
    const int p0 = blockIdx.x * 64, l0 = blockIdx.y * 64, bh = blockIdx.z;
#pragma unroll
    for (int i = 0; i < 16; i++) {
        const int lin = tid + i * 256;
        const int row = lin >> 6, col = lin & 63;
        Qs[row][col] = Qg[((size_t)((bh << 10) + l0 + row)) * DK + col];
        const int p = p0 + row;
        Rs[row][col] = (p < NREL) ? relk[p * DK + col] : 0.f;
    }
    __syncthreads();
    const int tx = tid & 15, ty = tid >> 4;
    float acc[4][4];
#pragma unroll
    for (int i = 0; i < 4; i++)
#pragma unroll
        for (int j = 0; j < 4; j++) acc[i][j] = 0.f;
#pragma unroll 8
    for (int k = 0; k < 64; k++) {
        float q[4], rv[4];
#pragma unroll
        for (int i = 0; i < 4; i++) q[i] = Qs[ty * 4 + i][k];
#pragma unroll
        for (int j = 0; j < 4; j++) rv[j] = Rs[tx * 4 + j][k];
#pragma unroll
        for (int i = 0; i < 4; i++)
#pragma unroll
            for (int j = 0; j < 4; j++) acc[i][j] += q[i] * rv[j];
    }
#pragma unroll
    for (int i = 0; i < 4; i++) {
        const int l = l0 + ty * 4 + i;
#pragma unroll
        for (int j = 0; j < 4; j++) {
            const int p = p0 + tx * 4 + j;
            if (p < NREL)
                Qrel[((size_t)((bh << 10) + l)) * NREL + p] = acc[i][j];
        }
    }
}

// ---------------- attn: mma.sync split-bf16 QK + softmax ----------------
#define AT_PITCH 1032                 // 1032 mod 32 = 8 -> conflict-free frag STS.64
#define SB_SBUF 0
#define SB_QH   (16*AT_PITCH*4)               // 66048
#define SB_QL   (SB_QH + 16*72*2)             // +2304
#define SB_KH   (SB_QL + 16*72*2)
#define SB_KL   (SB_KH + 128*72*2)            // +18432
#define SB_RED  (SB_KL + 128*72*2)
#define SB_ROWM (SB_RED + 256*4)
#define SB_ROWS (SB_ROWM + 64)
#define ATTN_SMEM_BYTES (SB_ROWS + 64)

__global__ __launch_bounds__(256) void attn_kernel(const __nv_bfloat16* __restrict__ Qhp,
                                                   const __nv_bfloat16* __restrict__ Qlp,
                                                   const __nv_bfloat16* __restrict__ Khp,
                                                   const __nv_bfloat16* __restrict__ Klp,
                                                   const float* __restrict__ Qrel,
                                                   const float* __restrict__ decay,
                                                   float* __restrict__ attn) {
    extern __shared__ char smc[];
    float* sbuf = (float*)(smc + SB_SBUF);
    float* red  = (float*)(smc + SB_RED);
    float* rowm = (float*)(smc + SB_ROWM);
    float* rows = (float*)(smc + SB_ROWS);
    const uint32_t sb = s2u(smc);

    const int tid = threadIdx.x, wid = tid >> 5, lane = tid & 31;
    const int bh = blockIdx.y, h = bh & 15;
    const int l0 = blockIdx.x * 16;
    const float dh = decay[h];

    // load Q tiles (16 rows x 32 uint32 each for hi/lo) into smem, pitch 72 bf16 = 36 u32
    {
        const uint32_t* qh32 = (const uint32_t*)(Qhp + ((size_t)(bh << 10) + l0) * 64);
        const uint32_t* ql32 = (const uint32_t*)(Qlp + ((size_t)(bh << 10) + l0) * 64);
#pragma unroll
        for (int i = 0; i < 2; i++) {
            const int lin = tid + i * 256;
            const int row = lin >> 5, c2 = lin & 31;
            ((uint32_t*)(smc + SB_QH))[row * 36 + c2] = qh32[row * 32 + c2];
            ((uint32_t*)(smc + SB_QL))[row * 36 + c2] = ql32[row * 32 + c2];
        }
    }
    __syncthreads();

    // per-warp Q fragments (reused across all key chunks)
    uint32_t ah[4][4], al[4][4];
#pragma unroll
    for (int kk = 0; kk < 4; kk++) {
        const uint32_t addr = sb + SB_QH + (((lane & 15)) * 72 + kk * 16 + (lane >> 4) * 8) * 2;
        ldm4(ah[kk], addr);
        ldm4(al[kk], addr + (SB_QL - SB_QH));
    }

    for (int ch = 0; ch < 8; ch++) {
        // load 128-key chunk hi/lo
        const uint32_t* kh32 = (const uint32_t*)(Khp + ((size_t)(bh << 10) + ch * 128) * 64);
        const uint32_t* kl32 = (const uint32_t*)(Klp + ((size_t)(bh << 10) + ch * 128) * 64);
#pragma unroll
        for (int i = 0; i < 16; i++) {
            const int lin = tid + i * 256;
            const int row = lin >> 5, c2 = lin & 31;
            ((uint32_t*)(smc + SB_KH))[row * 36 + c2] = kh32[row * 32 + c2];
            ((uint32_t*)(smc + SB_KL))[row * 36 + c2] = kl32[row * 32 + c2];
        }
        __syncthreads();

        float c[2][4];
#pragma unroll
        for (int nt = 0; nt < 2; nt++)
#pragma unroll
            for (int q = 0; q < 4; q++) c[nt][q] = 0.f;

#pragma unroll
        for (int kk = 0; kk < 4; kk++) {
            uint32_t kh4[4], kl4[4];
            const int mat = lane >> 3, rr8 = lane & 7;
            const int krow = wid * 16 + (mat >> 1) * 8 + rr8;
            const uint32_t addr = sb + SB_KH + (krow * 72 + kk * 16 + (mat & 1) * 8) * 2;
            ldm4(kh4, addr);
            ldm4(kl4, addr + (SB_KL - SB_KH));
#pragma unroll
            for (int nt = 0; nt < 2; nt++) {
                mma16816(c[nt], ah[kk], &kh4[nt * 2]);
                mma16816(c[nt], ah[kk], &kl4[nt * 2]);
                mma16816(c[nt], al[kk], &kh4[nt * 2]);
            }
        }

        // epilogue: bias + write scores to sbuf
        const int r1 = lane >> 2, cb = (lane & 3) * 2;
#pragma unroll
        for (int nt = 0; nt < 2; nt++) {
            const int colb = ch * 128 + wid * 16 + nt * 8 + cb;
#pragma unroll
            for (int half = 0; half < 2; half++) {
                const int row = r1 + half * 8;
                const int lg = l0 + row;
                const float* qr = Qrel + ((size_t)((bh << 10) + lg)) * NREL;
                const int rel0 = colb - lg;
                const int rel1 = rel0 + 1;
                const int rc0 = rel0 < -MAXREL ? -MAXREL : (rel0 > MAXREL ? MAXREL : rel0);
                const int rc1 = rel1 < -MAXREL ? -MAXREL : (rel1 > MAXREL ? MAXREL : rel1);
                float2 v;
                v.x = c[nt][half * 2 + 0] * 0.125f + __ldg(qr + rc0 + MAXREL)
                    - dh * fabsf((float)rel0);
                v.y = c[nt][half * 2 + 1] * 0.125f + __ldg(qr + rc1 + MAXREL)
                    - dh * fabsf((float)rel1);
                *(float2*)(sbuf + row * AT_PITCH + colb) = v;
            }
        }
        __syncthreads();
    }

    // softmax over 1024 cols per row; 16 threads per row
    const int row = tid >> 4, lane16 = tid & 15;
    float m = -3.0e38f;
    for (int j = 0; j < 64; j++) m = fmaxf(m, sbuf[row * AT_PITCH + lane16 + (j << 4)]);
    red[row * 16 + lane16] = m;
    __syncthreads();
    if (lane16 == 0) {
        float mm = red[row * 16];
        for (int j = 1; j < 16; j++) mm = fmaxf(mm, red[row * 16 + j]);
        rowm[row] = mm;
    }
    __syncthreads();
    const float mm = rowm[row];
    float sum = 0.f;
    for (int j = 0; j < 64; j++) {
        const int cidx = lane16 + (j << 4);
        const float e = __expf(sbuf[row * AT_PITCH + cidx] - mm);
        sbuf[row * AT_PITCH + cidx] = e;
        sum += e;
    }
    red[row * 16 + lane16] = sum;
    __syncthreads();
    if (lane16 == 0) {
        float ss = 0.f;
        for (int j = 0; j < 16; j++) ss += red[row * 16 + j];
        rows[row] = ss;
    }
    __syncthreads();

    for (int l = 0; l < 16; l++) {
        const float inv = 1.0f / rows[l];
        float* dst = attn + (((size_t)(bh << 10) + l0 + l) << 10);
#pragma unroll
        for (int j = 0; j < 4; j++) {
            const int cidx = tid + (j << 8);
            dst[cidx] = sbuf[l * AT_PITCH + cidx] * inv;
        }
    }
}

// ---------------- ctx: conflict-free float4 FFMA ----------------
#define CVP 68                         // pitch (floats): 68 mod 32 = 4, float4-aligned
#define AGP 260
__global__ __launch_bounds__(256) void ctx_kernel(const float* __restrict__ attn,
                                                  const float* __restrict__ Vg,
                                                  const float* __restrict__ relv,
                                                  float* __restrict__ ctx) {
    __shared__ float At[16 * CVP];
    __shared__ float Vs[64 * CVP];
    __shared__ float aggs[16 * AGP];

    const int tid = threadIdx.x;
    const int bh = blockIdx.y, b = bh >> 4, h = bh & 15;
    const int l0 = blockIdx.x * 16;

    for (int i = tid; i < 16 * AGP; i += 256) aggs[i] = 0.f;
    __syncthreads();

    const int row = tid >> 4, dq = tid & 15;     // 16 rows x 16 d-quads
    float4 acc = make_float4(0.f, 0.f, 0.f, 0.f);
    float c0 = 0.f, c1 = 0.f;

    for (int rc = 0; rc < 16; rc++) {
#pragma unroll
        for (int i = 0; i < 4; i++) {
            const int lin = tid + i * 256;
            const int ar = lin >> 6, ac = lin & 63;
            At[ar * CVP + ac] = attn[(((size_t)(bh << 10) + l0 + ar) << 10) + (rc << 6) + ac];
        }
#pragma unroll
        for (int i = 0; i < 16; i++) {
            const int lin = tid + i * 256;
            const int vr = lin >> 6, vc = lin & 63;
            Vs[vr * CVP + vc] = Vg[((size_t)((bh << 10) + (rc << 6) + vr)) * DK + vc];
        }
        __syncthreads();
        {
            const float* Ar = At + row * CVP;
#pragma unroll
            for (int q = 0; q < 16; q++) {
                const float4 a4 = *(const float4*)(Ar + q * 4);
                const float4 v0 = *(const float4*)(Vs + (q * 4 + 0) * CVP + dq * 4);
                const float4 v1 = *(const float4*)(Vs + (q * 4 + 1) * CVP + dq * 4);
                const float4 v2 = *(const float4*)(Vs + (q * 4 + 2) * CVP + dq * 4);
                const float4 v3 = *(const float4*)(Vs + (q * 4 + 3) * CVP + dq * 4);
                acc.x = fmaf(a4.x, v0.x, fmaf(a4.y, v1.x, fmaf(a4.z, v2.x, fmaf(a4.w, v3.x, acc.x))));
                acc.y = fmaf(a4.x, v0.y, fmaf(a4.y, v1.y, fmaf(a4.z, v2.y, fmaf(a4.w, v3.y, acc.y))));
                acc.z = fmaf(a4.x, v0.z, fmaf(a4.y, v1.z, fmaf(a4.z, v2.z, fmaf(a4.w, v3.z, acc.z))));
                acc.w = fmaf(a4.x, v0.w, fmaf(a4.y, v1.w, fmaf(a4.z, v2.w, fmaf(a4.w, v3.w, acc.w))));
            }
        }
        // bucket aggregation (unique writer per bucket)
#pragma unroll
        for (int jj = 0; jj < 4; jj++) {
            const int rr = dq + (jj << 4);
            const int r = (rc << 6) + rr;
            const float a = At[row * CVP + rr];
            const int rel = r - (l0 + row);
            if (rel <= -MAXREL)      c0 += a;
            else if (rel >= MAXREL)  c1 += a;
            else                     aggs[row * AGP + rel + MAXREL] = a;
        }
        __syncthreads();
    }
    atomicAdd(&aggs[row * AGP + 0], c0);
    atomicAdd(&aggs[row * AGP + 256], c1);
    __syncthreads();

    for (int p0 = 0; p0 < 256; p0 += 64) {
#pragma unroll
        for (int i = 0; i < 16; i++) {
            const int lin = tid + i * 256;
            const int vr = lin >> 6, vc = lin & 63;
            Vs[vr * CVP + vc] = relv[(p0 + vr) * DK + vc];
        }
        __syncthreads();
        {
            const float* Gr = aggs + row * AGP + p0;
#pragma unroll
            for (int q = 0; q < 16; q++) {
                const float4 g4 = *(const float4*)(Gr + q * 4);
                const float4 v0 = *(const float4*)(Vs + (q * 4 + 0) * CVP + dq * 4);
                const float4 v1 = *(const float4*)(Vs + (q * 4 + 1) * CVP + dq * 4);
                const float4 v2 = *(const float4*)(Vs + (q * 4 + 2) * CVP + dq * 4);
                const float4 v3 = *(const float4*)(Vs + (q * 4 + 3) * CVP + dq * 4);
                acc.x = fmaf(g4.x, v0.x, fmaf(g4.y, v1.x, fmaf(g4.z, v2.x, fmaf(g4.w, v3.x, acc.x))));
                acc.y = fmaf(g4.x, v0.y, fmaf(g4.y, v1.y, fmaf(g4.z, v2.y, fmaf(g4.w, v3.y, acc.y))));
                acc.z = fmaf(g4.x, v0.z, fmaf(g4.y, v1.z, fmaf(g4.z, v2.z, fmaf(g4.w, v3.z, acc.z))));
                acc.w = fmaf(g4.x, v0.w, fmaf(g4.y, v1.w, fmaf(g4.z, v2.w, fmaf(g4.w, v3.w, acc.w))));
            }
        }
        __syncthreads();
    }
    {
        const float4 rv = *(const float4*)(relv + 256 * DK + dq * 4);
        const float a = aggs[row * AGP + 256];
        acc.x = fmaf(a, rv.x, acc.x);
        acc.y = fmaf(a, rv.y, acc.y);
        acc.z = fmaf(a, rv.z, acc.z);
        acc.w = fmaf(a, rv.w, acc.w);
    }
    *(float4*)(ctx + (((size_t)(b << 10) + l0 + row) << 10) + (h << 6) + dq * 4) = acc;
}

// ---------------------------------------------------------------------------
extern "C" void kernel_launch(void* const* d_in, const int* in_sizes, int n_in,
                              void* d_out, int out_size) {
    const float* query = (const float*)d_in[0];
    const float* key_  = (const float*)d_in[1];
    const float* value = (const float*)d_in[2];
    const float* w_q   = (const float*)d_in[3];
    const float* w_k   = (const float*)d_in[4];
    const float* w_v   = (const float*)d_in[5];
    const float* w_o   = (const float*)d_in[6];
    const float* b_o   = (const float*)d_in[7];
    const float* rel_k = (const float*)d_in[8];
    const float* rel_v = (const float*)d_in[9];
    const float* decay = (const float*)d_in[10];

    float* out  = (float*)d_out;
    float* attn = out + (size_t)MTOT * DMODEL;

    float *Q, *K, *V, *Qrel, *ctx;
    __nv_bfloat16 *Ah, *Al, *Wh, *Wl, *Qh, *Ql, *Kh, *Kl, *Vh, *Vl;
    cudaGetSymbolAddress((void**)&Q,    g_Q);
    cudaGetSymbolAddress((void**)&K,    g_K);
    cudaGetSymbolAddress((void**)&V,    g_V);
    cudaGetSymbolAddress((void**)&Qrel, g_Qrel);
    cudaGetSymbolAddress((void**)&ctx,  g_ctx);
    cudaGetSymbolAddress((void**)&Ah,   g_Ah);
    cudaGetSymbolAddress((void**)&Al,   g_Al);
    cudaGetSymbolAddress((void**)&Wh,   g_Wh);
    cudaGetSymbolAddress((void**)&Wl,   g_Wl);
    cudaGetSymbolAddress((void**)&Qh,   g_Qh);
    cudaGetSymbolAddress((void**)&Ql,   g_Ql);
    cudaGetSymbolAddress((void**)&Kh,   g_Kh);
    cudaGetSymbolAddress((void**)&Kl,   g_Kl);
    cudaGetSymbolAddress((void**)&Vh,   g_Vh);
    cudaGetSymbolAddress((void**)&Vl,   g_Vl);

    cudaFuncSetAttribute(gemm_mma<0>, cudaFuncAttributeMaxDynamicSharedMemorySize, GEMM_SMEM);
    cudaFuncSetAttribute(gemm_mma<1>, cudaFuncAttributeMaxDynamicSharedMemorySize, GEMM_SMEM);
    cudaFuncSetAttribute(attn_kernel, cudaFuncAttributeMaxDynamicSharedMemorySize, ATTN_SMEM_BYTES);

    const int nA4 = MTOT * DMODEL / 4;
    const int nW4 = DMODEL * DMODEL / 4;
    const dim3 ggemm(DMODEL / 128, MTOT / 128);

    cvt_split<<<nA4 / 256, 256>>>((const float4*)query, (uint2*)Ah, (uint2*)Al);
    cvt_split<<<nW4 / 256, 256>>>((const float4*)w_q, (uint2*)Wh, (uint2*)Wl);
    gemm_mma<0><<<ggemm, 256, GEMM_SMEM>>>(Ah, Al, Wh, Wl, nullptr, Q, Qh, Ql);

    cvt_split<<<nA4 / 256, 256>>>((const float4*)key_, (uint2*)Ah, (uint2*)Al);
    cvt_split<<<nW4 / 256, 256>>>((const float4*)w_k, (uint2*)Wh, (uint2*)Wl);
    gemm_mma<0><<<ggemm, 256, GEMM_SMEM>>>(Ah, Al, Wh, Wl, nullptr, K, Kh, Kl);

    cvt_split<<<nA4 / 256, 256>>>((const float4*)value, (uint2*)Ah, (uint2*)Al);
    cvt_split<<<nW4 / 256, 256>>>((const float4*)w_v, (uint2*)Wh, (uint2*)Wl);
    gemm_mma<0><<<ggemm, 256, GEMM_SMEM>>>(Ah, Al, Wh, Wl, nullptr, V, Vh, Vl);

    qrel_kernel<<<dim3(5, 16, BH), 256>>>(Q, rel_k, Qrel);

    attn_kernel<<<dim3(SEQ / 16, BH), 256, ATTN_SMEM_BYTES>>>(Qh, Ql, Kh, Kl, Qrel, decay, attn);

    ctx_kernel<<<dim3(SEQ / 16, BH), 256>>>(attn, V, rel_v, ctx);

    cvt_split<<<nA4 / 256, 256>>>((const float4*)ctx, (uint2*)Ah, (uint2*)Al);
    cvt_split<<<nW4 / 256, 256>>>((const float4*)w_o, (uint2*)Wh, (uint2*)Wl);
    gemm_mma<1><<<ggemm, 256, GEMM_SMEM>>>(Ah, Al, Wh, Wl, b_o, out, nullptr, nullptr);
}

// round 9
// speedup vs baseline: 1.2662x; 1.0516x over previous
#include <cuda_runtime.h>
#include <cuda_bf16.h>
#include <math.h>
#include <stdint.h>

#define BATCH 8
#define SEQ   1024
#define DMODEL 1024
#define NHEADS 16
#define DK    64
#define NREL  257
#define MAXREL 128
#define MTOT  (BATCH*SEQ)
#define BH    (BATCH*NHEADS)

__device__ float g_Q[BH*SEQ*DK];
__device__ float g_K[BH*SEQ*DK];
__device__ float g_V[BH*SEQ*DK];
__device__ float g_Qrel[BH*SEQ*NREL];
__device__ float g_ctx[MTOT*DMODEL];
__device__ __nv_bfloat16 g_Ah[MTOT*DMODEL];
__device__ __nv_bfloat16 g_Al[MTOT*DMODEL];
__device__ __nv_bfloat16 g_Wh[DMODEL*DMODEL];
__device__ __nv_bfloat16 g_Wl[DMODEL*DMODEL];
__device__ __nv_bfloat16 g_Qh[BH*SEQ*DK];
__device__ __nv_bfloat16 g_Ql[BH*SEQ*DK];
__device__ __nv_bfloat16 g_Kh[BH*SEQ*DK];
__device__ __nv_bfloat16 g_Kl[BH*SEQ*DK];
__device__ __nv_bfloat16 g_Vh[BH*SEQ*DK];
__device__ __nv_bfloat16 g_Vl[BH*SEQ*DK];
__device__ __nv_bfloat16 g_agh[(size_t)BH*SEQ*272];
__device__ __nv_bfloat16 g_agl[(size_t)BH*SEQ*272];

// ---------------- helpers ----------------
__device__ __forceinline__ uint32_t s2u(const void* p) {
    uint32_t a;
    asm("{ .reg .u64 t; cvta.to.shared.u64 t, %1; cvt.u32.u64 %0, t; }" : "=r"(a) : "l"(p));
    return a;
}
__device__ __forceinline__ void cp16(uint32_t dst, const void* src) {
    asm volatile("cp.async.cg.shared.global [%0], [%1], 16;" :: "r"(dst), "l"(src) : "memory");
}
__device__ __forceinline__ void ldm4(uint32_t* r, uint32_t addr) {
    asm volatile("ldmatrix.sync.aligned.m8n8.x4.shared.b16 {%0,%1,%2,%3}, [%4];"
                 : "=r"(r[0]), "=r"(r[1]), "=r"(r[2]), "=r"(r[3]) : "r"(addr));
}
__device__ __forceinline__ void ldm4t(uint32_t* r, uint32_t addr) {
    asm volatile("ldmatrix.sync.aligned.m8n8.x4.trans.shared.b16 {%0,%1,%2,%3}, [%4];"
                 : "=r"(r[0]), "=r"(r[1]), "=r"(r[2]), "=r"(r[3]) : "r"(addr));
}
__device__ __forceinline__ void mma16816(float* d, const uint32_t* a, const uint32_t* b) {
    asm volatile(
        "mma.sync.aligned.m16n8k16.row.col.f32.bf16.bf16.f32 "
        "{%0,%1,%2,%3}, {%4,%5,%6,%7}, {%8,%9}, {%0,%1,%2,%3};"
        : "+f"(d[0]), "+f"(d[1]), "+f"(d[2]), "+f"(d[3])
        : "r"(a[0]), "r"(a[1]), "r"(a[2]), "r"(a[3]), "r"(b[0]), "r"(b[1]));
}
__device__ __forceinline__ uint32_t pack_hi(float a, float b) {
    __nv_bfloat16 h0 = __float2bfloat16(a), h1 = __float2bfloat16(b);
    return (uint32_t)__bfloat16_as_ushort(h0) | ((uint32_t)__bfloat16_as_ushort(h1) << 16);
}
__device__ __forceinline__ uint32_t pack_lo(float a, float b) {
    __nv_bfloat16 h0 = __float2bfloat16(a), h1 = __float2bfloat16(b);
    __nv_bfloat16 l0 = __float2bfloat16(a - __bfloat162float(h0));
    __nv_bfloat16 l1 = __float2bfloat16(b - __bfloat162float(h1));
    return (uint32_t)__bfloat16_as_ushort(l0) | ((uint32_t)__bfloat16_as_ushort(l1) << 16);
}

// ---------------- fp32 -> bf16 hi/lo split ----------------
__global__ __launch_bounds__(256) void cvt_split(const float4* __restrict__ x,
                                                 uint2* __restrict__ hi,
                                                 uint2* __restrict__ lo) {
    const int i = blockIdx.x * 256 + threadIdx.x;
    const float4 v = x[i];
    uint2 H, L;
    H.x = pack_hi(v.x, v.y); H.y = pack_hi(v.z, v.w);
    L.x = pack_lo(v.x, v.y); L.y = pack_lo(v.z, v.w);
    hi[i] = H;
    lo[i] = L;
}

// ---------------- mma.sync bf16 split GEMM ----------------
#define PITCH 72
#define MATB (128*PITCH*2)
#define STAGEB (4*MATB)
#define GEMM_SMEM (2*STAGEB)

template<int MODE>
__global__ __launch_bounds__(256, 1) void gemm_mma(const __nv_bfloat16* __restrict__ Ah,
                                                   const __nv_bfloat16* __restrict__ Al,
                                                   const __nv_bfloat16* __restrict__ Wh,
                                                   const __nv_bfloat16* __restrict__ Wl,
                                                   const float* __restrict__ bias,
                                                   float* __restrict__ out,
                                                   __nv_bfloat16* __restrict__ sh,
                                                   __nv_bfloat16* __restrict__ sl) {
    extern __shared__ char smc[];
    const uint32_t sb = s2u(smc);
    const int tid = threadIdx.x, wid = tid >> 5, lane = tid & 31;
    const int m0 = blockIdx.y * 128, n0 = blockIdx.x * 128;
    const int wm = wid >> 2, wn = wid & 3;

    float acc[4][4][4];
#pragma unroll
    for (int i = 0; i < 4; i++)
#pragma unroll
        for (int j = 0; j < 4; j++)
#pragma unroll
            for (int q = 0; q < 4; q++) acc[i][j][q] = 0.f;

    auto issue = [&](int s) {
        const uint32_t bu = sb + (s & 1) * STAGEB;
        const int k0 = s * 64;
#pragma unroll
        for (int it = 0; it < 4; it++) {
            const int idx = tid + it * 256;
            const int row = idx >> 3, j = idx & 7;
            const uint32_t doff = row * (PITCH * 2) + j * 16;
            const size_t ga = ((size_t)(m0 + row) * 1024 + k0 + j * 8) * 2;
            const size_t gw = ((size_t)(n0 + row) * 1024 + k0 + j * 8) * 2;
            cp16(bu + 0 * MATB + doff, (const char*)Ah + ga);
            cp16(bu + 1 * MATB + doff, (const char*)Al + ga);
            cp16(bu + 2 * MATB + doff, (const char*)Wh + gw);
            cp16(bu + 3 * MATB + doff, (const char*)Wl + gw);
        }
        asm volatile("cp.async.commit_group;" ::: "memory");
    };

    issue(0);
    for (int s = 0; s < 16; s++) {
        if (s + 1 < 16) {
            issue(s + 1);
            asm volatile("cp.async.wait_group 1;" ::: "memory");
        } else {
            asm volatile("cp.async.wait_group 0;" ::: "memory");
        }
        __syncthreads();
        const uint32_t bu = sb + (s & 1) * STAGEB;
#pragma unroll
        for (int kk = 0; kk < 4; kk++) {
            const int k16 = kk * 16;
            uint32_t ah[4][4], al[4][4];
#pragma unroll
            for (int i = 0; i < 4; i++) {
                const uint32_t addr = bu +
                    ((wm * 64 + i * 16 + (lane & 15)) * PITCH + k16 + (lane >> 4) * 8) * 2;
                ldm4(ah[i], addr);
                ldm4(al[i], addr + MATB);
            }
            uint32_t wh[2][4], wl[2][4];
#pragma unroll
            for (int j = 0; j < 2; j++) {
                const int mat = lane >> 3, rr = lane & 7;
                const int n = wn * 32 + j * 16 + (mat >> 1) * 8 + rr;
                const int k = k16 + (mat & 1) * 8;
                const uint32_t addr = bu + 2 * MATB + (n * PITCH + k) * 2;
                ldm4(wh[j], addr);
                ldm4(wl[j], addr + MATB);
            }
#pragma unroll
            for (int i = 0; i < 4; i++)
#pragma unroll
                for (int nt = 0; nt < 4; nt++) {
                    const uint32_t* bhf = &wh[nt >> 1][(nt & 1) * 2];
                    const uint32_t* blf = &wl[nt >> 1][(nt & 1) * 2];
                    mma16816(acc[i][nt], ah[i], bhf);
                    mma16816(acc[i][nt], ah[i], blf);
                    mma16816(acc[i][nt], al[i], bhf);
                }
        }
        __syncthreads();
    }

    const int rr = lane >> 2, cc = (lane & 3) * 2;
#pragma unroll
    for (int i = 0; i < 4; i++) {
#pragma unroll
        for (int nt = 0; nt < 4; nt++) {
            const int n = n0 + wn * 32 + nt * 8 + cc;
#pragma unroll
            for (int half = 0; half < 2; half++) {
                const int m = m0 + wm * 64 + i * 16 + rr + half * 8;
                float2 v;
                v.x = acc[i][nt][half * 2 + 0];
                v.y = acc[i][nt][half * 2 + 1];
                if (MODE == 0) {
                    const int b = m >> 10, sI = m & 1023, h = n >> 6, dd = n & 63;
                    const size_t off = (((size_t)(b * NHEADS + h) << 10) + sI) * 64 + dd;
                    *(float2*)(out + off) = v;
                    *(uint32_t*)(sh + off) = pack_hi(v.x, v.y);
                    *(uint32_t*)(sl + off) = pack_lo(v.x, v.y);
                } else {
                    v.x += bias[n];
                    v.y += bias[n + 1];
                    *(float2*)(out + (size_t)m * 1024 + n) = v;
                }
            }
        }
    }
}

// ---------------- Qrel (scalar, known-good) ----------------
__global__ __launch_bounds__(256) void qrel_kernel(const float* __restrict__ Qg,
                                                   const float* __restrict__ relk,
                                                   float* __restrict__ Qrel) {
    __shared__ float Qs[64][65];
    __shared__ float Rs[64][65];
    const int tid = threadIdx.x;
    const int p0 = blockIdx.x * 64, l0 = blockIdx.y * 64, bh = blockIdx.z;
#pragma unroll
    for (int i = 0; i < 16; i++) {
        const int lin = tid + i * 256;
        const int row = lin >> 6, col = lin & 63;
        Qs[row][col] = Qg[((size_t)((bh << 10) + l0 + row)) * DK + col];
        const int p = p0 + row;
        Rs[row][col] = (p < NREL) ? relk[p * DK + col] : 0.f;
    }
    __syncthreads();
    const int tx = tid & 15, ty = tid >> 4;
    float acc[4][4];
#pragma unroll
    for (int i = 0; i < 4; i++)
#pragma unroll
        for (int j = 0; j < 4; j++) acc[i][j] = 0.f;
#pragma unroll 8
    for (int k = 0; k < 64; k++) {
        float q[4], rv[4];
#pragma unroll
        for (int i = 0; i < 4; i++) q[i] = Qs[ty * 4 + i][k];
#pragma unroll
        for (int j = 0; j < 4; j++) rv[j] = Rs[tx * 4 + j][k];
#pragma unroll
        for (int i = 0; i < 4; i++)
#pragma unroll
            for (int j = 0; j < 4; j++) acc[i][j] += q[i] * rv[j];
    }
#pragma unroll
    for (int i = 0; i < 4; i++) {
        const int l = l0 + ty * 4 + i;
#pragma unroll
        for (int j = 0; j < 4; j++) {
            const int p = p0 + tx * 4 + j;
            if (p < NREL)
                Qrel[((size_t)((bh << 10) + l)) * NREL + p] = acc[i][j];
        }
    }
}

// ---------------- attn: mma QK + smem Qrel window + softmax + agg ----------------
#define AT_PITCH 1032
#define SB_SBUF 0
#define SB_QH   (16*AT_PITCH*4)
#define SB_QL   (SB_QH + 16*72*2)
#define SB_KH   (SB_QL + 16*72*2)
#define SB_KL   (SB_KH + 128*72*2)
#define SB_QW   (SB_KL + 128*72*2)
#define SB_AGG  (SB_QW + 16*264*4)
#define SB_RED  (SB_AGG + 16*272*4)
#define SB_ROWM (SB_RED + 256*4)
#define SB_ROWS (SB_ROWM + 64)
#define ATTN_SMEM_BYTES (SB_ROWS + 64)

__global__ __launch_bounds__(256) void attn_kernel(const __nv_bfloat16* __restrict__ Qhp,
                                                   const __nv_bfloat16* __restrict__ Qlp,
                                                   const __nv_bfloat16* __restrict__ Khp,
                                                   const __nv_bfloat16* __restrict__ Klp,
                                                   const float* __restrict__ Qrel,
                                                   const float* __restrict__ decay,
                                                   float* __restrict__ attn,
                                                   __nv_bfloat16* __restrict__ agh,
                                                   __nv_bfloat16* __restrict__ agl) {
    extern __shared__ char smc[];
    float* sbuf  = (float*)(smc + SB_SBUF);
    float* qw    = (float*)(smc + SB_QW);
    float* agg_s = (float*)(smc + SB_AGG);
    float* red   = (float*)(smc + SB_RED);
    float* rowm  = (float*)(smc + SB_ROWM);
    float* rows  = (float*)(smc + SB_ROWS);
    const uint32_t sb = s2u(smc);

    const int tid = threadIdx.x, wid = tid >> 5, lane = tid & 31;
    const int bh = blockIdx.y, h = bh & 15;
    const int l0 = blockIdx.x * 16;
    const float dh = decay[h];

    {
        const uint32_t* qh32 = (const uint32_t*)(Qhp + ((size_t)(bh << 10) + l0) * 64);
        const uint32_t* ql32 = (const uint32_t*)(Qlp + ((size_t)(bh << 10) + l0) * 64);
#pragma unroll
        for (int i = 0; i < 2; i++) {
            const int lin = tid + i * 256;
            const int row = lin >> 5, c2 = lin & 31;
            ((uint32_t*)(smc + SB_QH))[row * 36 + c2] = qh32[row * 32 + c2];
            ((uint32_t*)(smc + SB_QL))[row * 36 + c2] = ql32[row * 32 + c2];
        }
        const int qrow = tid >> 4, t16 = tid & 15;
        const float* src = Qrel + ((size_t)((bh << 10) + l0 + qrow)) * NREL;
        for (int p = t16; p < NREL; p += 16) qw[qrow * 264 + p] = src[p];
#pragma unroll
        for (int i = 0; i < 17; i++) {
            const int idx = tid + i * 256;
            if (idx < 16 * 272) agg_s[idx] = 0.f;
        }
    }
    __syncthreads();

    uint32_t ah[4][4], al[4][4];
#pragma unroll
    for (int kk = 0; kk < 4; kk++) {
        const uint32_t addr = sb + SB_QH + (((lane & 15)) * 72 + kk * 16 + (lane >> 4) * 8) * 2;
        ldm4(ah[kk], addr);
        ldm4(al[kk], addr + (SB_QL - SB_QH));
    }

    for (int ch = 0; ch < 8; ch++) {
        const uint32_t* kh32 = (const uint32_t*)(Khp + ((size_t)(bh << 10) + ch * 128) * 64);
        const uint32_t* kl32 = (const uint32_t*)(Klp + ((size_t)(bh << 10) + ch * 128) * 64);
#pragma unroll
        for (int i = 0; i < 16; i++) {
            const int lin = tid + i * 256;
            const int row = lin >> 5, c2 = lin & 31;
            ((uint32_t*)(smc + SB_KH))[row * 36 + c2] = kh32[row * 32 + c2];
            ((uint32_t*)(smc + SB_KL))[row * 36 + c2] = kl32[row * 32 + c2];
        }
        __syncthreads();

        float c[2][4];
#pragma unroll
        for (int nt = 0; nt < 2; nt++)
#pragma unroll
            for (int q = 0; q < 4; q++) c[nt][q] = 0.f;

#pragma unroll
        for (int kk = 0; kk < 4; kk++) {
            uint32_t kh4[4], kl4[4];
            const int mat = lane >> 3, rr8 = lane & 7;
            const int krow = wid * 16 + (mat >> 1) * 8 + rr8;
            const uint32_t addr = sb + SB_KH + (krow * 72 + kk * 16 + (mat & 1) * 8) * 2;
            ldm4(kh4, addr);
            ldm4(kl4, addr + (SB_KL - SB_KH));
#pragma unroll
            for (int nt = 0; nt < 2; nt++) {
                mma16816(c[nt], ah[kk], &kh4[nt * 2]);
                mma16816(c[nt], ah[kk], &kl4[nt * 2]);
                mma16816(c[nt], al[kk], &kh4[nt * 2]);
            }
        }

        const int r1 = lane >> 2, cb = (lane & 3) * 2;
#pragma unroll
        for (int nt = 0; nt < 2; nt++) {
            const int colb = ch * 128 + wid * 16 + nt * 8 + cb;
#pragma unroll
            for (int half = 0; half < 2; half++) {
                const int row = r1 + half * 8;
                const int lg = l0 + row;
                const int rel0 = colb - lg;
                const int rel1 = rel0 + 1;
                const int rc0 = rel0 < -MAXREL ? -MAXREL : (rel0 > MAXREL ? MAXREL : rel0);
                const int rc1 = rel1 < -MAXREL ? -MAXREL : (rel1 > MAXREL ? MAXREL : rel1);
                float2 v;
                v.x = c[nt][half * 2 + 0] * 0.125f + qw[row * 264 + rc0 + MAXREL]
                    - dh * fabsf((float)rel0);
                v.y = c[nt][half * 2 + 1] * 0.125f + qw[row * 264 + rc1 + MAXREL]
                    - dh * fabsf((float)rel1);
                *(float2*)(sbuf + row * AT_PITCH + colb) = v;
            }
        }
        __syncthreads();
    }

    const int row = tid >> 4, lane16 = tid & 15;
    float m = -3.0e38f;
    for (int j = 0; j < 64; j++) m = fmaxf(m, sbuf[row * AT_PITCH + lane16 + (j << 4)]);
    red[row * 16 + lane16] = m;
    __syncthreads();
    if (lane16 == 0) {
        float mm = red[row * 16];
        for (int j = 1; j < 16; j++) mm = fmaxf(mm, red[row * 16 + j]);
        rowm[row] = mm;
    }
    __syncthreads();
    const float mm = rowm[row];
    float sum = 0.f;
    for (int j = 0; j < 64; j++) {
        const int cidx = lane16 + (j << 4);
        const float e = __expf(sbuf[row * AT_PITCH + cidx] - mm);
        sbuf[row * AT_PITCH + cidx] = e;
        sum += e;
    }
    red[row * 16 + lane16] = sum;
    __syncthreads();
    if (lane16 == 0) {
        float ss = 0.f;
        for (int j = 0; j < 16; j++) ss += red[row * 16 + j];
        rows[row] = ss;
    }
    __syncthreads();

    {
        const int lg = l0 + row;
        float c0 = 0.f, c1 = 0.f;
        for (int j = 0; j < 64; j++) {
            const int r = lane16 + (j << 4);
            const float e = sbuf[row * AT_PITCH + r];
            const int rel = r - lg;
            if (rel <= -MAXREL)      c0 += e;
            else if (rel >= MAXREL)  c1 += e;
            else                     agg_s[row * 272 + rel + MAXREL] = e;
        }
        atomicAdd(&agg_s[row * 272 + 0], c0);
        atomicAdd(&agg_s[row * 272 + 256], c1);
    }
    __syncthreads();

#pragma unroll
    for (int k = 0; k < 16; k++) {
        const int i = tid + k * 256;
        const int r2 = i >> 8, p = i & 255;
        const float val = agg_s[r2 * 272 + p] * (1.0f / rows[r2]);
        const size_t off = ((size_t)(bh << 10) + l0 + r2) * 272 + p;
        __nv_bfloat16 hh = __float2bfloat16(val);
        agh[off] = hh;
        agl[off] = __float2bfloat16(val - __bfloat162float(hh));
    }
    {
        const int r2 = tid >> 4, p = 256 + (tid & 15);
        const float val = agg_s[r2 * 272 + p] * (1.0f / rows[r2]);
        const size_t off = ((size_t)(bh << 10) + l0 + r2) * 272 + p;
        __nv_bfloat16 hh = __float2bfloat16(val);
        agh[off] = hh;
        agl[off] = __float2bfloat16(val - __bfloat162float(hh));
    }

    for (int l = 0; l < 16; l++) {
        const float inv = 1.0f / rows[l];
        float* dst = attn + (((size_t)(bh << 10) + l0 + l) << 10);
#pragma unroll
        for (int j = 0; j < 4; j++) {
            const int cidx = tid + (j << 8);
            dst[cidx] = sbuf[l * AT_PITCH + cidx] * inv;
        }
    }
}

// ---------------- ctx: split-bf16 mma (A@V fused with agg@rel_v) ----------------
#define CP   136
#define CPB  (CP*2)
#define C_AH 0
#define C_AL (128*CPB)
#define C_VH (2*128*CPB)
#define C_VL (C_VH + 128*72*2)
#define C_RH (C_VL + 128*72*2)
#define C_RL (C_RH + 64*280*2)
#define CTX_SMEM (C_RL + 64*280*2)

__global__ __launch_bounds__(256, 1) void ctx_mma(const float* __restrict__ attn,
                                                  const __nv_bfloat16* __restrict__ Vh,
                                                  const __nv_bfloat16* __restrict__ Vl,
                                                  const __nv_bfloat16* __restrict__ agh,
                                                  const __nv_bfloat16* __restrict__ agl,
                                                  const float* __restrict__ relv,
                                                  float* __restrict__ ctx) {
    extern __shared__ char smc[];
    const uint32_t sb = s2u(smc);
    const int tid = threadIdx.x, wid = tid >> 5, lane = tid & 31;
    const int bh = blockIdx.y, b = bh >> 4, h = bh & 15;
    const int l0 = blockIdx.x * 128;
    const int wm = wid >> 1, wn = wid & 1;

    for (int i = tid; i < (64 * 280 * 2 * 2) / 4; i += 256)
        ((uint32_t*)(smc + C_RH))[i] = 0u;
    __syncthreads();
    for (int i = tid; i < NREL * 64; i += 256) {
        const int p = i >> 6, d = i & 63;
        const float v = relv[i];
        __nv_bfloat16 hh = __float2bfloat16(v);
        *(__nv_bfloat16*)(smc + C_RH + (d * 280 + p) * 2) = hh;
        *(__nv_bfloat16*)(smc + C_RL + (d * 280 + p) * 2) =
            __float2bfloat16(v - __bfloat162float(hh));
    }

    float c[2][4][4];
#pragma unroll
    for (int i = 0; i < 2; i++)
#pragma unroll
        for (int j = 0; j < 4; j++)
#pragma unroll
            for (int q = 0; q < 4; q++) c[i][j][q] = 0.f;

    for (int ck = 0; ck < 11; ck++) {
        const int KS = (ck == 10) ? 1 : 8;
        __syncthreads();
        if (ck < 8) {
#pragma unroll
            for (int it = 0; it < 16; it++) {
                const int idx = tid + it * 256;
                const int row = idx >> 5, c4 = idx & 31;
                const float4 v = *(const float4*)(attn +
                    (((size_t)(bh << 10) + l0 + row) << 10) + ck * 128 + c4 * 4);
                *(uint2*)(smc + C_AH + row * CPB + c4 * 8) =
                    make_uint2(pack_hi(v.x, v.y), pack_hi(v.z, v.w));
                *(uint2*)(smc + C_AL + row * CPB + c4 * 8) =
                    make_uint2(pack_lo(v.x, v.y), pack_lo(v.z, v.w));
            }
#pragma unroll
            for (int it = 0; it < 4; it++) {
                const int idx = tid + it * 256;
                const int row = idx >> 3, j = idx & 7;
                const size_t src = ((size_t)(bh << 10) + ck * 128 + row) * 64 + j * 8;
                *(uint4*)(smc + C_VH + row * 144 + j * 16) = *(const uint4*)((const char*)Vh + src * 2);
                *(uint4*)(smc + C_VL + row * 144 + j * 16) = *(const uint4*)((const char*)Vl + src * 2);
            }
        } else if (ck < 10) {
            const int p0 = (ck - 8) * 128;
#pragma unroll
            for (int it = 0; it < 8; it++) {
                const int idx = tid + it * 256;
                const int row = idx >> 4, j = idx & 15;
                const size_t src = ((size_t)(bh << 10) + l0 + row) * 272 + p0 + j * 8;
                *(uint4*)(smc + C_AH + row * CPB + j * 16) = *(const uint4*)((const char*)agh + src * 2);
                *(uint4*)(smc + C_AL + row * CPB + j * 16) = *(const uint4*)((const char*)agl + src * 2);
            }
        } else {
            const int idx = tid;
            const int row = idx >> 1, j = idx & 1;
            const size_t src = ((size_t)(bh << 10) + l0 + row) * 272 + 256 + j * 8;
            *(uint4*)(smc + C_AH + row * CPB + j * 16) = *(const uint4*)((const char*)agh + src * 2);
            *(uint4*)(smc + C_AL + row * CPB + j * 16) = *(const uint4*)((const char*)agl + src * 2);
        }
        __syncthreads();

        const int p0 = (ck >= 8) ? (ck - 8) * 128 : 0;
        for (int kk = 0; kk < KS; kk++) {
            uint32_t a_h[2][4], a_l[2][4];
#pragma unroll
            for (int i = 0; i < 2; i++) {
                const uint32_t addr = sb + C_AH +
                    ((wm * 32 + i * 16 + (lane & 15)) * CP + kk * 16 + (lane >> 4) * 8) * 2;
                ldm4(a_h[i], addr);
                ldm4(a_l[i], addr + (C_AL - C_AH));
            }
            uint32_t b_h[2][4], b_l[2][4];
            const int mat = lane >> 3, rr8 = lane & 7;
            if (ck < 8) {
#pragma unroll
                for (int nb = 0; nb < 2; nb++) {
                    const uint32_t addr = sb + C_VH +
                        ((kk * 16 + (mat & 1) * 8 + rr8) * 72 + wn * 32 + nb * 16 + (mat >> 1) * 8) * 2;
                    ldm4t(b_h[nb], addr);
                    ldm4t(b_l[nb], addr + (C_VL - C_VH));
                }
            } else {
#pragma unroll
                for (int nb = 0; nb < 2; nb++) {
                    const uint32_t addr = sb + C_RH +
                        ((wn * 32 + nb * 16 + (mat >> 1) * 8 + rr8) * 280 + p0 + kk * 16 + (mat & 1) * 8) * 2;
                    ldm4(b_h[nb], addr);
                    ldm4(b_l[nb], addr + (C_RL - C_RH));
                }
            }
#pragma unroll
            for (int i = 0; i < 2; i++)
#pragma unroll
                for (int nb = 0; nb < 2; nb++)
#pragma unroll
                    for (int half = 0; half < 2; half++) {
                        const int j = nb * 2 + half;
                        mma16816(c[i][j], a_h[i], &b_h[nb][half * 2]);
                        mma16816(c[i][j], a_h[i], &b_l[nb][half * 2]);
                        mma16816(c[i][j], a_l[i], &b_h[nb][half * 2]);
                    }
        }
    }

    const int rr = lane >> 2, cc = (lane & 3) * 2;
#pragma unroll
    for (int i = 0; i < 2; i++)
#pragma unroll
        for (int j = 0; j < 4; j++)
#pragma unroll
            for (int half = 0; half < 2; half++) {
                const int m = l0 + wm * 32 + i * 16 + rr + half * 8;
                const int d = wn * 32 + j * 8 + cc;
                float2 v;
                v.x = c[i][j][half * 2 + 0];
                v.y = c[i][j][half * 2 + 1];
                *(float2*)(ctx + ((size_t)(b << 10) + m) * 1024 + h * 64 + d) = v;
            }
}

// ---------------------------------------------------------------------------
extern "C" void kernel_launch(void* const* d_in, const int* in_sizes, int n_in,
                              void* d_out, int out_size) {
    const float* query = (const float*)d_in[0];
    const float* key_  = (const float*)d_in[1];
    const float* value = (const float*)d_in[2];
    const float* w_q   = (const float*)d_in[3];
    const float* w_k   = (const float*)d_in[4];
    const float* w_v   = (const float*)d_in[5];
    const float* w_o   = (const float*)d_in[6];
    const float* b_o   = (const float*)d_in[7];
    const float* rel_k = (const float*)d_in[8];
    const float* rel_v = (const float*)d_in[9];
    const float* decay = (const float*)d_in[10];

    float* out  = (float*)d_out;
    float* attn = out + (size_t)MTOT * DMODEL;

    float *Q, *K, *V, *Qrel, *ctx;
    __nv_bfloat16 *Ah, *Al, *Wh, *Wl, *Qh, *Ql, *Kh, *Kl, *Vh, *Vl, *agh, *agl;
    cudaGetSymbolAddress((void**)&Q,    g_Q);
    cudaGetSymbolAddress((void**)&K,    g_K);
    cudaGetSymbolAddress((void**)&V,    g_V);
    cudaGetSymbolAddress((void**)&Qrel, g_Qrel);
    cudaGetSymbolAddress((void**)&ctx,  g_ctx);
    cudaGetSymbolAddress((void**)&Ah,   g_Ah);
    cudaGetSymbolAddress((void**)&Al,   g_Al);
    cudaGetSymbolAddress((void**)&Wh,   g_Wh);
    cudaGetSymbolAddress((void**)&Wl,   g_Wl);
    cudaGetSymbolAddress((void**)&Qh,   g_Qh);
    cudaGetSymbolAddress((void**)&Ql,   g_Ql);
    cudaGetSymbolAddress((void**)&Kh,   g_Kh);
    cudaGetSymbolAddress((void**)&Kl,   g_Kl);
    cudaGetSymbolAddress((void**)&Vh,   g_Vh);
    cudaGetSymbolAddress((void**)&Vl,   g_Vl);
    cudaGetSymbolAddress((void**)&agh,  g_agh);
    cudaGetSymbolAddress((void**)&agl,  g_agl);

    cudaFuncSetAttribute(gemm_mma<0>, cudaFuncAttributeMaxDynamicSharedMemorySize, GEMM_SMEM);
    cudaFuncSetAttribute(gemm_mma<1>, cudaFuncAttributeMaxDynamicSharedMemorySize, GEMM_SMEM);
    cudaFuncSetAttribute(attn_kernel, cudaFuncAttributeMaxDynamicSharedMemorySize, ATTN_SMEM_BYTES);
    cudaFuncSetAttribute(ctx_mma, cudaFuncAttributeMaxDynamicSharedMemorySize, CTX_SMEM);

    const int nA4 = MTOT * DMODEL / 4;
    const int nW4 = DMODEL * DMODEL / 4;
    const dim3 ggemm(DMODEL / 128, MTOT / 128);

    cvt_split<<<nA4 / 256, 256>>>((const float4*)query, (uint2*)Ah, (uint2*)Al);
    cvt_split<<<nW4 / 256, 256>>>((const float4*)w_q, (uint2*)Wh, (uint2*)Wl);
    gemm_mma<0><<<ggemm, 256, GEMM_SMEM>>>(Ah, Al, Wh, Wl, nullptr, Q, Qh, Ql);

    cvt_split<<<nA4 / 256, 256>>>((const float4*)key_, (uint2*)Ah, (uint2*)Al);
    cvt_split<<<nW4 / 256, 256>>>((const float4*)w_k, (uint2*)Wh, (uint2*)Wl);
    gemm_mma<0><<<ggemm, 256, GEMM_SMEM>>>(Ah, Al, Wh, Wl, nullptr, K, Kh, Kl);

    cvt_split<<<nA4 / 256, 256>>>((const float4*)value, (uint2*)Ah, (uint2*)Al);
    cvt_split<<<nW4 / 256, 256>>>((const float4*)w_v, (uint2*)Wh, (uint2*)Wl);
    gemm_mma<0><<<ggemm, 256, GEMM_SMEM>>>(Ah, Al, Wh, Wl, nullptr, V, Vh, Vl);

    qrel_kernel<<<dim3(5, 16, BH), 256>>>(Q, rel_k, Qrel);

    attn_kernel<<<dim3(SEQ / 16, BH), 256, ATTN_SMEM_BYTES>>>(Qh, Ql, Kh, Kl, Qrel, decay,
                                                              attn, agh, agl);

    ctx_mma<<<dim3(SEQ / 128, BH), 256, CTX_SMEM>>>(attn, Vh, Vl, agh, agl, rel_v, ctx);

    cvt_split<<<nA4 / 256, 256>>>((const float4*)ctx, (uint2*)Ah, (uint2*)Al);
    cvt_split<<<nW4 / 256, 256>>>((const float4*)w_o, (uint2*)Wh, (uint2*)Wl);
    gemm_mma<1><<<ggemm, 256, GEMM_SMEM>>>(Ah, Al, Wh, Wl, b_o, out, nullptr, nullptr);
}

// round 12
// speedup vs baseline: 1.7343x; 1.3697x over previous
#include <cuda_runtime.h>
#include <cuda_bf16.h>
#include <math.h>
#include <stdint.h>

#define BATCH 8
#define SEQ   1024
#define DMODEL 1024
#define NHEADS 16
#define DK    64
#define NREL  257
#define MAXREL 128
#define MTOT  (BATCH*SEQ)
#define BH    (BATCH*NHEADS)

__device__ float g_ctx[MTOT*DMODEL];
__device__ __nv_bfloat16 g_Ah[MTOT*DMODEL];
__device__ __nv_bfloat16 g_Al[MTOT*DMODEL];
__device__ __nv_bfloat16 g_Wh[DMODEL*DMODEL];
__device__ __nv_bfloat16 g_Wl[DMODEL*DMODEL];
__device__ __nv_bfloat16 g_Qh[BH*SEQ*DK];
__device__ __nv_bfloat16 g_Ql[BH*SEQ*DK];
__device__ __nv_bfloat16 g_Kh[BH*SEQ*DK];
__device__ __nv_bfloat16 g_Kl[BH*SEQ*DK];
__device__ __nv_bfloat16 g_Vh[BH*SEQ*DK];
__device__ __nv_bfloat16 g_Vl[BH*SEQ*DK];
__device__ __nv_bfloat16 g_rkh[NREL*DK + 64];
__device__ __nv_bfloat16 g_rkl[NREL*DK + 64];
__device__ __nv_bfloat16 g_agh[(size_t)BH*SEQ*272];
__device__ __nv_bfloat16 g_agl[(size_t)BH*SEQ*272];

// ---------------- helpers ----------------
__device__ __forceinline__ uint32_t s2u(const void* p) {
    uint32_t a;
    asm("{ .reg .u64 t; cvta.to.shared.u64 t, %1; cvt.u32.u64 %0, t; }" : "=r"(a) : "l"(p));
    return a;
}
__device__ __forceinline__ void cp16(uint32_t dst, const void* src) {
    asm volatile("cp.async.cg.shared.global [%0], [%1], 16;" :: "r"(dst), "l"(src) : "memory");
}
__device__ __forceinline__ void ldm4(uint32_t* r, uint32_t addr) {
    asm volatile("ldmatrix.sync.aligned.m8n8.x4.shared.b16 {%0,%1,%2,%3}, [%4];"
                 : "=r"(r[0]), "=r"(r[1]), "=r"(r[2]), "=r"(r[3]) : "r"(addr));
}
__device__ __forceinline__ void ldm4t(uint32_t* r, uint32_t addr) {
    asm volatile("ldmatrix.sync.aligned.m8n8.x4.trans.shared.b16 {%0,%1,%2,%3}, [%4];"
                 : "=r"(r[0]), "=r"(r[1]), "=r"(r[2]), "=r"(r[3]) : "r"(addr));
}
__device__ __forceinline__ void mma16816(float* d, const uint32_t* a, const uint32_t* b) {
    asm volatile(
        "mma.sync.aligned.m16n8k16.row.col.f32.bf16.bf16.f32 "
        "{%0,%1,%2,%3}, {%4,%5,%6,%7}, {%8,%9}, {%0,%1,%2,%3};"
        : "+f"(d[0]), "+f"(d[1]), "+f"(d[2]), "+f"(d[3])
        : "r"(a[0]), "r"(a[1]), "r"(a[2]), "r"(a[3]), "r"(b[0]), "r"(b[1]));
}
__device__ __forceinline__ uint32_t pack_hi(float a, float b) {
    __nv_bfloat16 h0 = __float2bfloat16(a), h1 = __float2bfloat16(b);
    return (uint32_t)__bfloat16_as_ushort(h0) | ((uint32_t)__bfloat16_as_ushort(h1) << 16);
}
__device__ __forceinline__ uint32_t pack_lo(float a, float b) {
    __nv_bfloat16 h0 = __float2bfloat16(a), h1 = __float2bfloat16(b);
    __nv_bfloat16 l0 = __float2bfloat16(a - __bfloat162float(h0));
    __nv_bfloat16 l1 = __float2bfloat16(b - __bfloat162float(h1));
    return (uint32_t)__bfloat16_as_ushort(l0) | ((uint32_t)__bfloat16_as_ushort(l1) << 16);
}

// ---------------- fp32 -> bf16 hi/lo split (guarded) ----------------
__global__ __launch_bounds__(256) void cvt_split(const float4* __restrict__ x,
                                                 uint2* __restrict__ hi,
                                                 uint2* __restrict__ lo,
                                                 int n4) {
    const int i = blockIdx.x * 256 + threadIdx.x;
    if (i >= n4) return;
    const float4 v = x[i];
    uint2 H, L;
    H.x = pack_hi(v.x, v.y); H.y = pack_hi(v.z, v.w);
    L.x = pack_lo(v.x, v.y); L.y = pack_lo(v.z, v.w);
    hi[i] = H;
    lo[i] = L;
}

// ---------------- mma.sync bf16 split GEMM ----------------
#define PITCH 72
#define MATB (128*PITCH*2)
#define STAGEB (4*MATB)
#define GEMM_SMEM (2*STAGEB)

template<int MODE>
__global__ __launch_bounds__(256, 1) void gemm_mma(const __nv_bfloat16* __restrict__ Ah,
                                                   const __nv_bfloat16* __restrict__ Al,
                                                   const __nv_bfloat16* __restrict__ Wh,
                                                   const __nv_bfloat16* __restrict__ Wl,
                                                   const float* __restrict__ bias,
                                                   float* __restrict__ out,
                                                   __nv_bfloat16* __restrict__ sh,
                                                   __nv_bfloat16* __restrict__ sl) {
    extern __shared__ char smc[];
    const uint32_t sb = s2u(smc);
    const int tid = threadIdx.x, wid = tid >> 5, lane = tid & 31;
    const int m0 = blockIdx.y * 128, n0 = blockIdx.x * 128;
    const int wm = wid >> 2, wn = wid & 3;

    float acc[4][4][4];
#pragma unroll
    for (int i = 0; i < 4; i++)
#pragma unroll
        for (int j = 0; j < 4; j++)
#pragma unroll
            for (int q = 0; q < 4; q++) acc[i][j][q] = 0.f;

    auto issue = [&](int s) {
        const uint32_t bu = sb + (s & 1) * STAGEB;
        const int k0 = s * 64;
#pragma unroll
        for (int it = 0; it < 4; it++) {
            const int idx = tid + it * 256;
            const int row = idx >> 3, j = idx & 7;
            const uint32_t doff = row * (PITCH * 2) + j * 16;
            const size_t ga = ((size_t)(m0 + row) * 1024 + k0 + j * 8) * 2;
            const size_t gw = ((size_t)(n0 + row) * 1024 + k0 + j * 8) * 2;
            cp16(bu + 0 * MATB + doff, (const char*)Ah + ga);
            cp16(bu + 1 * MATB + doff, (const char*)Al + ga);
            cp16(bu + 2 * MATB + doff, (const char*)Wh + gw);
            cp16(bu + 3 * MATB + doff, (const char*)Wl + gw);
        }
        asm volatile("cp.async.commit_group;" ::: "memory");
    };

    issue(0);
    for (int s = 0; s < 16; s++) {
        if (s + 1 < 16) {
            issue(s + 1);
            asm volatile("cp.async.wait_group 1;" ::: "memory");
        } else {
            asm volatile("cp.async.wait_group 0;" ::: "memory");
        }
        __syncthreads();
        const uint32_t bu = sb + (s & 1) * STAGEB;
#pragma unroll
        for (int kk = 0; kk < 4; kk++) {
            const int k16 = kk * 16;
            uint32_t ah[4][4], al[4][4];
#pragma unroll
            for (int i = 0; i < 4; i++) {
                const uint32_t addr = bu +
                    ((wm * 64 + i * 16 + (lane & 15)) * PITCH + k16 + (lane >> 4) * 8) * 2;
                ldm4(ah[i], addr);
                ldm4(al[i], addr + MATB);
            }
            uint32_t wh[2][4], wl[2][4];
#pragma unroll
            for (int j = 0; j < 2; j++) {
                const int mat = lane >> 3, rr = lane & 7;
                const int n = wn * 32 + j * 16 + (mat >> 1) * 8 + rr;
                const int k = k16 + (mat & 1) * 8;
                const uint32_t addr = bu + 2 * MATB + (n * PITCH + k) * 2;
                ldm4(wh[j], addr);
                ldm4(wl[j], addr + MATB);
            }
#pragma unroll
            for (int i = 0; i < 4; i++)
#pragma unroll
                for (int nt = 0; nt < 4; nt++) {
                    const uint32_t* bhf = &wh[nt >> 1][(nt & 1) * 2];
                    const uint32_t* blf = &wl[nt >> 1][(nt & 1) * 2];
                    mma16816(acc[i][nt], ah[i], bhf);
                    mma16816(acc[i][nt], ah[i], blf);
                    mma16816(acc[i][nt], al[i], bhf);
                }
        }
        __syncthreads();
    }

    const int rr = lane >> 2, cc = (lane & 3) * 2;
#pragma unroll
    for (int i = 0; i < 4; i++) {
#pragma unroll
        for (int nt = 0; nt < 4; nt++) {
            const int n = n0 + wn * 32 + nt * 8 + cc;
#pragma unroll
            for (int half = 0; half < 2; half++) {
                const int m = m0 + wm * 64 + i * 16 + rr + half * 8;
                float2 v;
                v.x = acc[i][nt][half * 2 + 0];
                v.y = acc[i][nt][half * 2 + 1];
                if (MODE == 0) {
                    const int b = m >> 10, sI = m & 1023, h = n >> 6, dd = n & 63;
                    const size_t off = (((size_t)(b * NHEADS + h) << 10) + sI) * 64 + dd;
                    *(uint32_t*)(sh + off) = pack_hi(v.x, v.y);
                    *(uint32_t*)(sl + off) = pack_lo(v.x, v.y);
                } else {
                    v.x += bias[n];
                    v.y += bias[n + 1];
                    *(float2*)(out + (size_t)m * 1024 + n) = v;
                }
            }
        }
    }
}

// ---------------- attn: mma QK + fused qrel mma + softmax + agg ----------------
#define AT_PITCH 1032
#define SB_SBUF 0
#define SB_QH   (16*AT_PITCH*4)
#define SB_QL   (SB_QH + 16*72*2)
#define SB_KH   (SB_QL + 16*72*2)
#define SB_KL   (SB_KH + 128*72*2)
#define SB_QW   (SB_KL + 128*72*2)
#define SB_AGG  (SB_QW + 16*264*4)
#define SB_RED  (SB_AGG + 16*272*4)
#define SB_ROWM (SB_RED + 256*4)
#define SB_ROWS (SB_ROWM + 64)
#define ATTN_SMEM_BYTES (SB_ROWS + 64)

__global__ __launch_bounds__(256) void attn_kernel(const __nv_bfloat16* __restrict__ Qhp,
                                                   const __nv_bfloat16* __restrict__ Qlp,
                                                   const __nv_bfloat16* __restrict__ Khp,
                                                   const __nv_bfloat16* __restrict__ Klp,
                                                   const __nv_bfloat16* __restrict__ rkh,
                                                   const __nv_bfloat16* __restrict__ rkl,
                                                   const float* __restrict__ decay,
                                                   float* __restrict__ attn,
                                                   __nv_bfloat16* __restrict__ agh,
                                                   __nv_bfloat16* __restrict__ agl) {
    extern __shared__ char smc[];
    float* sbuf  = (float*)(smc + SB_SBUF);
    float* qw    = (float*)(smc + SB_QW);
    float* agg_s = (float*)(smc + SB_AGG);
    float* red   = (float*)(smc + SB_RED);
    float* rowm  = (float*)(smc + SB_ROWM);
    float* rows  = (float*)(smc + SB_ROWS);
    const uint32_t sb = s2u(smc);

    const int tid = threadIdx.x, wid = tid >> 5, lane = tid & 31;
    const int bh = blockIdx.y, h = bh & 15;
    const int l0 = blockIdx.x * 16;
    const float dh = decay[h];

    {
        const uint32_t* qh32 = (const uint32_t*)(Qhp + ((size_t)(bh << 10) + l0) * 64);
        const uint32_t* ql32 = (const uint32_t*)(Qlp + ((size_t)(bh << 10) + l0) * 64);
#pragma unroll
        for (int i = 0; i < 2; i++) {
            const int lin = tid + i * 256;
            const int row = lin >> 5, c2 = lin & 31;
            ((uint32_t*)(smc + SB_QH))[row * 36 + c2] = qh32[row * 32 + c2];
            ((uint32_t*)(smc + SB_QL))[row * 36 + c2] = ql32[row * 32 + c2];
        }
#pragma unroll
        for (int i = 0; i < 17; i++) {
            const int idx = tid + i * 256;
            if (idx < 16 * 272) agg_s[idx] = 0.f;
        }
    }
    __syncthreads();

    uint32_t ah[4][4], al[4][4];
#pragma unroll
    for (int kk = 0; kk < 4; kk++) {
        const uint32_t addr = sb + SB_QH + (((lane & 15)) * 72 + kk * 16 + (lane >> 4) * 8) * 2;
        ldm4(ah[kk], addr);
        ldm4(al[kk], addr + (SB_QL - SB_QH));
    }

    // fused qrel: qw[16][257] = Q @ rel_k^T via 3 mma chunks through K buffers
    for (int rc3 = 0; rc3 < 3; rc3++) {
        const int p0c = rc3 * 128;
#pragma unroll
        for (int i = 0; i < 16; i++) {
            const int lin = tid + i * 256;
            const int row = lin >> 5, c2 = lin & 31;
            const int p = p0c + row;
            uint32_t vh = 0u, vl = 0u;
            if (p < NREL) {
                vh = ((const uint32_t*)rkh)[p * 32 + c2];
                vl = ((const uint32_t*)rkl)[p * 32 + c2];
            }
            ((uint32_t*)(smc + SB_KH))[row * 36 + c2] = vh;
            ((uint32_t*)(smc + SB_KL))[row * 36 + c2] = vl;
        }
        __syncthreads();
        float c[2][4];
#pragma unroll
        for (int nt = 0; nt < 2; nt++)
#pragma unroll
            for (int q = 0; q < 4; q++) c[nt][q] = 0.f;
#pragma unroll
        for (int kk = 0; kk < 4; kk++) {
            uint32_t kh4[4], kl4[4];
            const int mat = lane >> 3, rr8 = lane & 7;
            const int krow = wid * 16 + (mat >> 1) * 8 + rr8;
            const uint32_t addr = sb + SB_KH + (krow * 72 + kk * 16 + (mat & 1) * 8) * 2;
            ldm4(kh4, addr);
            ldm4(kl4, addr + (SB_KL - SB_KH));
#pragma unroll
            for (int nt = 0; nt < 2; nt++) {
                mma16816(c[nt], ah[kk], &kh4[nt * 2]);
                mma16816(c[nt], ah[kk], &kl4[nt * 2]);
                mma16816(c[nt], al[kk], &kh4[nt * 2]);
            }
        }
        const int r1 = lane >> 2, cb = (lane & 3) * 2;
#pragma unroll
        for (int nt = 0; nt < 2; nt++) {
            const int colb = p0c + wid * 16 + nt * 8 + cb;
#pragma unroll
            for (int half = 0; half < 2; half++) {
                const int row = r1 + half * 8;
                if (colb < NREL)     qw[row * 264 + colb]     = c[nt][half * 2 + 0];
                if (colb + 1 < NREL) qw[row * 264 + colb + 1] = c[nt][half * 2 + 1];
            }
        }
        __syncthreads();
    }

    // QK chunks
    for (int ch = 0; ch < 8; ch++) {
        const uint32_t* kh32 = (const uint32_t*)(Khp + ((size_t)(bh << 10) + ch * 128) * 64);
        const uint32_t* kl32 = (const uint32_t*)(Klp + ((size_t)(bh << 10) + ch * 128) * 64);
#pragma unroll
        for (int i = 0; i < 16; i++) {
            const int lin = tid + i * 256;
            const int row = lin >> 5, c2 = lin & 31;
            ((uint32_t*)(smc + SB_KH))[row * 36 + c2] = kh32[row * 32 + c2];
            ((uint32_t*)(smc + SB_KL))[row * 36 + c2] = kl32[row * 32 + c2];
        }
        __syncthreads();

        float c[2][4];
#pragma unroll
        for (int nt = 0; nt < 2; nt++)
#pragma unroll
            for (int q = 0; q < 4; q++) c[nt][q] = 0.f;

#pragma unroll
        for (int kk = 0; kk < 4; kk++) {
            uint32_t kh4[4], kl4[4];
            const int mat = lane >> 3, rr8 = lane & 7;
            const int krow = wid * 16 + (mat >> 1) * 8 + rr8;
            const uint32_t addr = sb + SB_KH + (krow * 72 + kk * 16 + (mat & 1) * 8) * 2;
            ldm4(kh4, addr);
            ldm4(kl4, addr + (SB_KL - SB_KH));
#pragma unroll
            for (int nt = 0; nt < 2; nt++) {
                mma16816(c[nt], ah[kk], &kh4[nt * 2]);
                mma16816(c[nt], ah[kk], &kl4[nt * 2]);
                mma16816(c[nt], al[kk], &kh4[nt * 2]);
            }
        }

        const int r1 = lane >> 2, cb = (lane & 3) * 2;
#pragma unroll
        for (int nt = 0; nt < 2; nt++) {
            const int colb = ch * 128 + wid * 16 + nt * 8 + cb;
#pragma unroll
            for (int half = 0; half < 2; half++) {
                const int row = r1 + half * 8;
                const int lg = l0 + row;
                const int rel0 = colb - lg;
                const int rel1 = rel0 + 1;
                const int rc0 = rel0 < -MAXREL ? -MAXREL : (rel0 > MAXREL ? MAXREL : rel0);
                const int rc1 = rel1 < -MAXREL ? -MAXREL : (rel1 > MAXREL ? MAXREL : rel1);
                float2 v;
                v.x = c[nt][half * 2 + 0] * 0.125f + qw[row * 264 + rc0 + MAXREL]
                    - dh * fabsf((float)rel0);
                v.y = c[nt][half * 2 + 1] * 0.125f + qw[row * 264 + rc1 + MAXREL]
                    - dh * fabsf((float)rel1);
                *(float2*)(sbuf + row * AT_PITCH + colb) = v;
            }
        }
        __syncthreads();
    }

    // softmax
    const int row = tid >> 4, lane16 = tid & 15;
    float m = -3.0e38f;
    for (int j = 0; j < 64; j++) m = fmaxf(m, sbuf[row * AT_PITCH + lane16 + (j << 4)]);
    red[row * 16 + lane16] = m;
    __syncthreads();
    if (lane16 == 0) {
        float mm = red[row * 16];
        for (int j = 1; j < 16; j++) mm = fmaxf(mm, red[row * 16 + j]);
        rowm[row] = mm;
    }
    __syncthreads();
    const float mm = rowm[row];
    float sum = 0.f;
    for (int j = 0; j < 64; j++) {
        const int cidx = lane16 + (j << 4);
        const float e = __expf(sbuf[row * AT_PITCH + cidx] - mm);
        sbuf[row * AT_PITCH + cidx] = e;
        sum += e;
    }
    red[row * 16 + lane16] = sum;
    __syncthreads();
    if (lane16 == 0) {
        float ss = 0.f;
        for (int j = 0; j < 16; j++) ss += red[row * 16 + j];
        rows[row] = ss;
    }
    __syncthreads();

    // bucket aggregation
    {
        const int lg = l0 + row;
        float c0 = 0.f, c1 = 0.f;
        for (int j = 0; j < 64; j++) {
            const int r = lane16 + (j << 4);
            const float e = sbuf[row * AT_PITCH + r];
            const int rel = r - lg;
            if (rel <= -MAXREL)      c0 += e;
            else if (rel >= MAXREL)  c1 += e;
            else                     agg_s[row * 272 + rel + MAXREL] = e;
        }
        atomicAdd(&agg_s[row * 272 + 0], c0);
        atomicAdd(&agg_s[row * 272 + 256], c1);
    }
    __syncthreads();

#pragma unroll
    for (int k = 0; k < 16; k++) {
        const int i = tid + k * 256;
        const int r2 = i >> 8, p = i & 255;
        const float val = agg_s[r2 * 272 + p] * (1.0f / rows[r2]);
        const size_t off = ((size_t)(bh << 10) + l0 + r2) * 272 + p;
        __nv_bfloat16 hh = __float2bfloat16(val);
        agh[off] = hh;
        agl[off] = __float2bfloat16(val - __bfloat162float(hh));
    }
    {
        const int r2 = tid >> 4, p = 256 + (tid & 15);
        const float val = agg_s[r2 * 272 + p] * (1.0f / rows[r2]);
        const size_t off = ((size_t)(bh << 10) + l0 + r2) * 272 + p;
        __nv_bfloat16 hh = __float2bfloat16(val);
        agh[off] = hh;
        agl[off] = __float2bfloat16(val - __bfloat162float(hh));
    }

    for (int l = 0; l < 16; l++) {
        const float inv = 1.0f / rows[l];
        float* dst = attn + (((size_t)(bh << 10) + l0 + l) << 10);
#pragma unroll
        for (int j = 0; j < 4; j++) {
            const int cidx = tid + (j << 8);
            dst[cidx] = sbuf[l * AT_PITCH + cidx] * inv;
        }
    }
}

// ---------------- ctx: split-bf16 mma, slim smem (2 CTAs/SM) ----------------
#define CP   136
#define CPB  (CP*2)
#define RVP  136                       // relv staging pitch (bf16): >=128 chunk + pad
#define C_AH 0
#define C_AL (128*CPB)                 // 34816
#define C_VH (2*128*CPB)               // 69632
#define C_VL (C_VH + 128*72*2)         // 88064  (V tile 18432 B >= 64*RVP*2 = 17408)
#define CTX_SMEM (C_VL + 128*72*2)     // 106496

__global__ __launch_bounds__(256, 2) void ctx_mma(const float* __restrict__ attn,
                                                  const __nv_bfloat16* __restrict__ Vh,
                                                  const __nv_bfloat16* __restrict__ Vl,
                                                  const __nv_bfloat16* __restrict__ agh,
                                                  const __nv_bfloat16* __restrict__ agl,
                                                  const float* __restrict__ relv,
                                                  float* __restrict__ ctx) {
    extern __shared__ char smc[];
    const uint32_t sb = s2u(smc);
    const int tid = threadIdx.x, wid = tid >> 5, lane = tid & 31;
    const int bh = blockIdx.y, b = bh >> 4, h = bh & 15;
    const int l0 = blockIdx.x * 128;
    const int wm = wid >> 1, wn = wid & 1;

    float c[2][4][4];
#pragma unroll
    for (int i = 0; i < 2; i++)
#pragma unroll
        for (int j = 0; j < 4; j++)
#pragma unroll
            for (int q = 0; q < 4; q++) c[i][j][q] = 0.f;

    for (int ck = 0; ck < 11; ck++) {
        const int KS = (ck == 10) ? 1 : 8;
        __syncthreads();
        if (ck < 8) {
            // attn fp32 -> bf16 hi/lo A tiles
#pragma unroll
            for (int it = 0; it < 16; it++) {
                const int idx = tid + it * 256;
                const int row = idx >> 5, c4 = idx & 31;
                const float4 v = *(const float4*)(attn +
                    (((size_t)(bh << 10) + l0 + row) << 10) + ck * 128 + c4 * 4);
                *(uint2*)(smc + C_AH + row * CPB + c4 * 8) =
                    make_uint2(pack_hi(v.x, v.y), pack_hi(v.z, v.w));
                *(uint2*)(smc + C_AL + row * CPB + c4 * 8) =
                    make_uint2(pack_lo(v.x, v.y), pack_lo(v.z, v.w));
            }
            // V tiles [seq][d] pitch 72
#pragma unroll
            for (int it = 0; it < 4; it++) {
                const int idx = tid + it * 256;
                const int row = idx >> 3, j = idx & 7;
                const size_t src = ((size_t)(bh << 10) + ck * 128 + row) * 64 + j * 8;
                *(uint4*)(smc + C_VH + row * 144 + j * 16) = *(const uint4*)((const char*)Vh + src * 2);
                *(uint4*)(smc + C_VL + row * 144 + j * 16) = *(const uint4*)((const char*)Vl + src * 2);
            }
        } else if (ck < 10) {
            const int p0 = (ck - 8) * 128;
            // agg A tiles
#pragma unroll
            for (int it = 0; it < 8; it++) {
                const int idx = tid + it * 256;
                const int row = idx >> 4, j = idx & 15;
                const size_t src = ((size_t)(bh << 10) + l0 + row) * 272 + p0 + j * 8;
                *(uint4*)(smc + C_AH + row * CPB + j * 16) = *(const uint4*)((const char*)agh + src * 2);
                *(uint4*)(smc + C_AL + row * CPB + j * 16) = *(const uint4*)((const char*)agl + src * 2);
            }
            // relv chunk transposed into V buffers: [d][p-local] pitch RVP=136
#pragma unroll
            for (int it = 0; it < 32; it++) {
                const int idx = tid + it * 256;
                const int d = idx >> 7, p = idx & 127;
                const float v = relv[(size_t)(p0 + p) * 64 + d];
                __nv_bfloat16 hh = __float2bfloat16(v);
                *(__nv_bfloat16*)(smc + C_VH + (d * RVP + p) * 2) = hh;
                *(__nv_bfloat16*)(smc + C_VL + (d * RVP + p) * 2) =
                    __float2bfloat16(v - __bfloat162float(hh));
            }
        } else {
            // agg tail cols 256..271
            const int row = tid >> 1, j = tid & 1;
            const size_t src = ((size_t)(bh << 10) + l0 + row) * 272 + 256 + j * 8;
            *(uint4*)(smc + C_AH + row * CPB + j * 16) = *(const uint4*)((const char*)agh + src * 2);
            *(uint4*)(smc + C_AL + row * CPB + j * 16) = *(const uint4*)((const char*)agl + src * 2);
            // relv tail: zero 64 rows x 16 cols (pitch RVP), then col0 = relv[256][d]
#pragma unroll
            for (int it = 0; it < 2; it++) {
                const int idx = tid + it * 256;
                const int d = idx >> 3, jj = idx & 7;
                ((uint32_t*)(smc + C_VH))[d * (RVP / 2) + jj] = 0u;
                ((uint32_t*)(smc + C_VL))[d * (RVP / 2) + jj] = 0u;
            }
            __syncthreads();
            if (tid < 64) {
                const float v = relv[(size_t)256 * 64 + tid];
                __nv_bfloat16 hh = __float2bfloat16(v);
                *(__nv_bfloat16*)(smc + C_VH + (tid * RVP) * 2) = hh;
                *(__nv_bfloat16*)(smc + C_VL + (tid * RVP) * 2) =
                    __float2bfloat16(v - __bfloat162float(hh));
            }
        }
        __syncthreads();

        for (int kk = 0; kk < KS; kk++) {
            uint32_t a_h[2][4], a_l[2][4];
#pragma unroll
            for (int i = 0; i < 2; i++) {
                const uint32_t addr = sb + C_AH +
                    ((wm * 32 + i * 16 + (lane & 15)) * CP + kk * 16 + (lane >> 4) * 8) * 2;
                ldm4(a_h[i], addr);
                ldm4(a_l[i], addr + (C_AL - C_AH));
            }
            uint32_t b_h[2][4], b_l[2][4];
            const int mat = lane >> 3, rr8 = lane & 7;
            if (ck < 8) {
#pragma unroll
                for (int nb = 0; nb < 2; nb++) {
                    const uint32_t addr = sb + C_VH +
                        ((kk * 16 + (mat & 1) * 8 + rr8) * 72 + wn * 32 + nb * 16 + (mat >> 1) * 8) * 2;
                    ldm4t(b_h[nb], addr);
                    ldm4t(b_l[nb], addr + (C_VL - C_VH));
                }
            } else {
#pragma unroll
                for (int nb = 0; nb < 2; nb++) {
                    const uint32_t addr = sb + C_VH +
                        ((wn * 32 + nb * 16 + (mat >> 1) * 8 + rr8) * RVP + kk * 16 + (mat & 1) * 8) * 2;
                    ldm4(b_h[nb], addr);
                    ldm4(b_l[nb], addr + (C_VL - C_VH));
                }
            }
#pragma unroll
            for (int i = 0; i < 2; i++)
#pragma unroll
                for (int nb = 0; nb < 2; nb++)
#pragma unroll
                    for (int half = 0; half < 2; half++) {
                        const int j = nb * 2 + half;
                        mma16816(c[i][j], a_h[i], &b_h[nb][half * 2]);
                        mma16816(c[i][j], a_h[i], &b_l[nb][half * 2]);
                        mma16816(c[i][j], a_l[i], &b_h[nb][half * 2]);
                    }
        }
    }

    const int rr = lane >> 2, cc = (lane & 3) * 2;
#pragma unroll
    for (int i = 0; i < 2; i++)
#pragma unroll
        for (int j = 0; j < 4; j++)
#pragma unroll
            for (int half = 0; half < 2; half++) {
                const int m = l0 + wm * 32 + i * 16 + rr + half * 8;
                const int d = wn * 32 + j * 8 + cc;
                float2 v;
                v.x = c[i][j][half * 2 + 0];
                v.y = c[i][j][half * 2 + 1];
                *(float2*)(ctx + ((size_t)(b << 10) + m) * 1024 + h * 64 + d) = v;
            }
}

// ---------------------------------------------------------------------------
extern "C" void kernel_launch(void* const* d_in, const int* in_sizes, int n_in,
                              void* d_out, int out_size) {
    const float* query = (const float*)d_in[0];
    const float* key_  = (const float*)d_in[1];
    const float* value = (const float*)d_in[2];
    const float* w_q   = (const float*)d_in[3];
    const float* w_k   = (const float*)d_in[4];
    const float* w_v   = (const float*)d_in[5];
    const float* w_o   = (const float*)d_in[6];
    const float* b_o   = (const float*)d_in[7];
    const float* rel_k = (const float*)d_in[8];
    const float* rel_v = (const float*)d_in[9];
    const float* decay = (const float*)d_in[10];

    float* out  = (float*)d_out;
    float* attn = out + (size_t)MTOT * DMODEL;

    float *ctx;
    __nv_bfloat16 *Ah, *Al, *Wh, *Wl, *Qh, *Ql, *Kh, *Kl, *Vh, *Vl, *rkh, *rkl, *agh, *agl;
    cudaGetSymbolAddress((void**)&ctx,  g_ctx);
    cudaGetSymbolAddress((void**)&Ah,   g_Ah);
    cudaGetSymbolAddress((void**)&Al,   g_Al);
    cudaGetSymbolAddress((void**)&Wh,   g_Wh);
    cudaGetSymbolAddress((void**)&Wl,   g_Wl);
    cudaGetSymbolAddress((void**)&Qh,   g_Qh);
    cudaGetSymbolAddress((void**)&Ql,   g_Ql);
    cudaGetSymbolAddress((void**)&Kh,   g_Kh);
    cudaGetSymbolAddress((void**)&Kl,   g_Kl);
    cudaGetSymbolAddress((void**)&Vh,   g_Vh);
    cudaGetSymbolAddress((void**)&Vl,   g_Vl);
    cudaGetSymbolAddress((void**)&rkh,  g_rkh);
    cudaGetSymbolAddress((void**)&rkl,  g_rkl);
    cudaGetSymbolAddress((void**)&agh,  g_agh);
    cudaGetSymbolAddress((void**)&agl,  g_agl);

    cudaFuncSetAttribute(gemm_mma<0>, cudaFuncAttributeMaxDynamicSharedMemorySize, GEMM_SMEM);
    cudaFuncSetAttribute(gemm_mma<1>, cudaFuncAttributeMaxDynamicSharedMemorySize, GEMM_SMEM);
    cudaFuncSetAttribute(attn_kernel, cudaFuncAttributeMaxDynamicSharedMemorySize, ATTN_SMEM_BYTES);
    cudaFuncSetAttribute(ctx_mma, cudaFuncAttributeMaxDynamicSharedMemorySize, CTX_SMEM);

    const int nA4 = MTOT * DMODEL / 4;
    const int nW4 = DMODEL * DMODEL / 4;
    const int nR4 = NREL * DK / 4;
    const dim3 ggemm(DMODEL / 128, MTOT / 128);

    cvt_split<<<nA4 / 256, 256>>>((const float4*)query, (uint2*)Ah, (uint2*)Al, nA4);
    cvt_split<<<nW4 / 256, 256>>>((const float4*)w_q, (uint2*)Wh, (uint2*)Wl, nW4);
    gemm_mma<0><<<ggemm, 256, GEMM_SMEM>>>(Ah, Al, Wh, Wl, nullptr, nullptr, Qh, Ql);

    cvt_split<<<nA4 / 256, 256>>>((const float4*)key_, (uint2*)Ah, (uint2*)Al, nA4);
    cvt_split<<<nW4 / 256, 256>>>((const float4*)w_k, (uint2*)Wh, (uint2*)Wl, nW4);
    gemm_mma<0><<<ggemm, 256, GEMM_SMEM>>>(Ah, Al, Wh, Wl, nullptr, nullptr, Kh, Kl);

    cvt_split<<<nA4 / 256, 256>>>((const float4*)value, (uint2*)Ah, (uint2*)Al, nA4);
    cvt_split<<<nW4 / 256, 256>>>((const float4*)w_v, (uint2*)Wh, (uint2*)Wl, nW4);
    gemm_mma<0><<<ggemm, 256, GEMM_SMEM>>>(Ah, Al, Wh, Wl, nullptr, nullptr, Vh, Vl);

    cvt_split<<<(nR4 + 255) / 256, 256>>>((const float4*)rel_k, (uint2*)rkh, (uint2*)rkl, nR4);

    attn_kernel<<<dim3(SEQ / 16, BH), 256, ATTN_SMEM_BYTES>>>(Qh, Ql, Kh, Kl, rkh, rkl,
                                                              decay, attn, agh, agl);

    ctx_mma<<<dim3(SEQ / 128, BH), 256, CTX_SMEM>>>(attn, Vh, Vl, agh, agl, rel_v, ctx);

    cvt_split<<<nA4 / 256, 256>>>((const float4*)ctx, (uint2*)Ah, (uint2*)Al, nA4);
    cvt_split<<<nW4 / 256, 256>>>((const float4*)w_o, (uint2*)Wh, (uint2*)Wl, nW4);
    gemm_mma<1><<<ggemm, 256, GEMM_SMEM>>>(Ah, Al, Wh, Wl, b_o, out, nullptr, nullptr);
}

// round 13
// speedup vs baseline: 1.9386x; 1.1178x over previous
#include <cuda_runtime.h>
#include <cuda_bf16.h>
#include <math.h>
#include <stdint.h>

#define BATCH 8
#define SEQ   1024
#define DMODEL 1024
#define NHEADS 16
#define DK    64
#define NREL  257
#define MAXREL 128
#define MTOT  (BATCH*SEQ)
#define BH    (BATCH*NHEADS)

__device__ float g_ctx[MTOT*DMODEL];
__device__ __nv_bfloat16 g_Ah[MTOT*DMODEL];
__device__ __nv_bfloat16 g_Al[MTOT*DMODEL];
__device__ __nv_bfloat16 g_Wh[DMODEL*DMODEL];
__device__ __nv_bfloat16 g_Wl[DMODEL*DMODEL];
__device__ __nv_bfloat16 g_Qh[BH*SEQ*DK];
__device__ __nv_bfloat16 g_Ql[BH*SEQ*DK];
__device__ __nv_bfloat16 g_Kh[BH*SEQ*DK];
__device__ __nv_bfloat16 g_Kl[BH*SEQ*DK];
__device__ __nv_bfloat16 g_Vh[BH*SEQ*DK];
__device__ __nv_bfloat16 g_Vl[BH*SEQ*DK];
__device__ __nv_bfloat16 g_rkh[NREL*DK + 64];
__device__ __nv_bfloat16 g_rkl[NREL*DK + 64];
__device__ __nv_bfloat16 g_agh[(size_t)BH*SEQ*272];
__device__ __nv_bfloat16 g_agl[(size_t)BH*SEQ*272];

// ---------------- helpers ----------------
__device__ __forceinline__ uint32_t s2u(const void* p) {
    uint32_t a;
    asm("{ .reg .u64 t; cvta.to.shared.u64 t, %1; cvt.u32.u64 %0, t; }" : "=r"(a) : "l"(p));
    return a;
}
__device__ __forceinline__ void cp16(uint32_t dst, const void* src) {
    asm volatile("cp.async.cg.shared.global [%0], [%1], 16;" :: "r"(dst), "l"(src) : "memory");
}
__device__ __forceinline__ void cp_commit_wait() {
    asm volatile("cp.async.commit_group;" ::: "memory");
    asm volatile("cp.async.wait_group 0;" ::: "memory");
}
__device__ __forceinline__ void ldm4(uint32_t* r, uint32_t addr) {
    asm volatile("ldmatrix.sync.aligned.m8n8.x4.shared.b16 {%0,%1,%2,%3}, [%4];"
                 : "=r"(r[0]), "=r"(r[1]), "=r"(r[2]), "=r"(r[3]) : "r"(addr));
}
__device__ __forceinline__ void ldm4t(uint32_t* r, uint32_t addr) {
    asm volatile("ldmatrix.sync.aligned.m8n8.x4.trans.shared.b16 {%0,%1,%2,%3}, [%4];"
                 : "=r"(r[0]), "=r"(r[1]), "=r"(r[2]), "=r"(r[3]) : "r"(addr));
}
__device__ __forceinline__ void mma16816(float* d, const uint32_t* a, const uint32_t* b) {
    asm volatile(
        "mma.sync.aligned.m16n8k16.row.col.f32.bf16.bf16.f32 "
        "{%0,%1,%2,%3}, {%4,%5,%6,%7}, {%8,%9}, {%0,%1,%2,%3};"
        : "+f"(d[0]), "+f"(d[1]), "+f"(d[2]), "+f"(d[3])
        : "r"(a[0]), "r"(a[1]), "r"(a[2]), "r"(a[3]), "r"(b[0]), "r"(b[1]));
}
__device__ __forceinline__ uint32_t pack_hi(float a, float b) {
    __nv_bfloat16 h0 = __float2bfloat16(a), h1 = __float2bfloat16(b);
    return (uint32_t)__bfloat16_as_ushort(h0) | ((uint32_t)__bfloat16_as_ushort(h1) << 16);
}
__device__ __forceinline__ uint32_t pack_lo(float a, float b) {
    __nv_bfloat16 h0 = __float2bfloat16(a), h1 = __float2bfloat16(b);
    __nv_bfloat16 l0 = __float2bfloat16(a - __bfloat162float(h0));
    __nv_bfloat16 l1 = __float2bfloat16(b - __bfloat162float(h1));
    return (uint32_t)__bfloat16_as_ushort(l0) | ((uint32_t)__bfloat16_as_ushort(l1) << 16);
}

// ---------------- fp32 -> bf16 hi/lo split (guarded) ----------------
__global__ __launch_bounds__(256) void cvt_split(const float4* __restrict__ x,
                                                 uint2* __restrict__ hi,
                                                 uint2* __restrict__ lo,
                                                 int n4) {
    const int i = blockIdx.x * 256 + threadIdx.x;
    if (i >= n4) return;
    const float4 v = x[i];
    uint2 H, L;
    H.x = pack_hi(v.x, v.y); H.y = pack_hi(v.z, v.w);
    L.x = pack_lo(v.x, v.y); L.y = pack_lo(v.z, v.w);
    hi[i] = H;
    lo[i] = L;
}

// ---------------- mma.sync bf16 split GEMM (R12, unchanged) ----------------
#define PITCH 72
#define MATB (128*PITCH*2)
#define STAGEB (4*MATB)
#define GEMM_SMEM (2*STAGEB)

template<int MODE>
__global__ __launch_bounds__(256, 1) void gemm_mma(const __nv_bfloat16* __restrict__ Ah,
                                                   const __nv_bfloat16* __restrict__ Al,
                                                   const __nv_bfloat16* __restrict__ Wh,
                                                   const __nv_bfloat16* __restrict__ Wl,
                                                   const float* __restrict__ bias,
                                                   float* __restrict__ out,
                                                   __nv_bfloat16* __restrict__ sh,
                                                   __nv_bfloat16* __restrict__ sl) {
    extern __shared__ char smc[];
    const uint32_t sb = s2u(smc);
    const int tid = threadIdx.x, wid = tid >> 5, lane = tid & 31;
    const int m0 = blockIdx.y * 128, n0 = blockIdx.x * 128;
    const int wm = wid >> 2, wn = wid & 3;

    float acc[4][4][4];
#pragma unroll
    for (int i = 0; i < 4; i++)
#pragma unroll
        for (int j = 0; j < 4; j++)
#pragma unroll
            for (int q = 0; q < 4; q++) acc[i][j][q] = 0.f;

    auto issue = [&](int s) {
        const uint32_t bu = sb + (s & 1) * STAGEB;
        const int k0 = s * 64;
#pragma unroll
        for (int it = 0; it < 4; it++) {
            const int idx = tid + it * 256;
            const int row = idx >> 3, j = idx & 7;
            const uint32_t doff = row * (PITCH * 2) + j * 16;
            const size_t ga = ((size_t)(m0 + row) * 1024 + k0 + j * 8) * 2;
            const size_t gw = ((size_t)(n0 + row) * 1024 + k0 + j * 8) * 2;
            cp16(bu + 0 * MATB + doff, (const char*)Ah + ga);
            cp16(bu + 1 * MATB + doff, (const char*)Al + ga);
            cp16(bu + 2 * MATB + doff, (const char*)Wh + gw);
            cp16(bu + 3 * MATB + doff, (const char*)Wl + gw);
        }
        asm volatile("cp.async.commit_group;" ::: "memory");
    };

    issue(0);
    for (int s = 0; s < 16; s++) {
        if (s + 1 < 16) {
            issue(s + 1);
            asm volatile("cp.async.wait_group 1;" ::: "memory");
        } else {
            asm volatile("cp.async.wait_group 0;" ::: "memory");
        }
        __syncthreads();
        const uint32_t bu = sb + (s & 1) * STAGEB;
#pragma unroll
        for (int kk = 0; kk < 4; kk++) {
            const int k16 = kk * 16;
            uint32_t ah[4][4], al[4][4];
#pragma unroll
            for (int i = 0; i < 4; i++) {
                const uint32_t addr = bu +
                    ((wm * 64 + i * 16 + (lane & 15)) * PITCH + k16 + (lane >> 4) * 8) * 2;
                ldm4(ah[i], addr);
                ldm4(al[i], addr + MATB);
            }
            uint32_t wh[2][4], wl[2][4];
#pragma unroll
            for (int j = 0; j < 2; j++) {
                const int mat = lane >> 3, rr = lane & 7;
                const int n = wn * 32 + j * 16 + (mat >> 1) * 8 + rr;
                const int k = k16 + (mat & 1) * 8;
                const uint32_t addr = bu + 2 * MATB + (n * PITCH + k) * 2;
                ldm4(wh[j], addr);
                ldm4(wl[j], addr + MATB);
            }
#pragma unroll
            for (int i = 0; i < 4; i++)
#pragma unroll
                for (int nt = 0; nt < 4; nt++) {
                    const uint32_t* bhf = &wh[nt >> 1][(nt & 1) * 2];
                    const uint32_t* blf = &wl[nt >> 1][(nt & 1) * 2];
                    mma16816(acc[i][nt], ah[i], bhf);
                    mma16816(acc[i][nt], ah[i], blf);
                    mma16816(acc[i][nt], al[i], bhf);
                }
        }
        __syncthreads();
    }

    const int rr = lane >> 2, cc = (lane & 3) * 2;
#pragma unroll
    for (int i = 0; i < 4; i++) {
#pragma unroll
        for (int nt = 0; nt < 4; nt++) {
            const int n = n0 + wn * 32 + nt * 8 + cc;
#pragma unroll
            for (int half = 0; half < 2; half++) {
                const int m = m0 + wm * 64 + i * 16 + rr + half * 8;
                float2 v;
                v.x = acc[i][nt][half * 2 + 0];
                v.y = acc[i][nt][half * 2 + 1];
                if (MODE == 0) {
                    const int b = m >> 10, sI = m & 1023, h = n >> 6, dd = n & 63;
                    const size_t off = (((size_t)(b * NHEADS + h) << 10) + sI) * 64 + dd;
                    *(uint32_t*)(sh + off) = pack_hi(v.x, v.y);
                    *(uint32_t*)(sl + off) = pack_lo(v.x, v.y);
                } else {
                    v.x += bias[n];
                    v.y += bias[n + 1];
                    *(float2*)(out + (size_t)m * 1024 + n) = v;
                }
            }
        }
    }
}

// ---------------- attn: 64-key chunks, qw/agg union, 2 CTAs/SM ----------------
#define AT_PITCH 1032
#define SB_SBUF 0
#define SB_QH   (16*AT_PITCH*4)               // 66048
#define SB_QL   (SB_QH + 2304)
#define SB_KH   (SB_QL + 2304)                // 70656
#define SB_KL   (SB_KH + 64*72*2)             // +9216
#define SB_UN   (SB_KL + 64*72*2)             // 89088 : qw(16x264 f32) / agg(16x272 f32)
#define SB_RED  (SB_UN + 16*272*4)            // 106496
#define SB_ROWM (SB_RED + 1024)
#define SB_ROWS (SB_ROWM + 64)
#define ATTN_SMEM_BYTES (SB_ROWS + 64)        // 107648 -> 2 CTAs/SM

__global__ __launch_bounds__(256, 2) void attn_kernel(const __nv_bfloat16* __restrict__ Qhp,
                                                      const __nv_bfloat16* __restrict__ Qlp,
                                                      const __nv_bfloat16* __restrict__ Khp,
                                                      const __nv_bfloat16* __restrict__ Klp,
                                                      const __nv_bfloat16* __restrict__ rkh,
                                                      const __nv_bfloat16* __restrict__ rkl,
                                                      const float* __restrict__ decay,
                                                      float* __restrict__ attn,
                                                      __nv_bfloat16* __restrict__ agh,
                                                      __nv_bfloat16* __restrict__ agl) {
    extern __shared__ char smc[];
    float* sbuf  = (float*)(smc + SB_SBUF);
    float* qw    = (float*)(smc + SB_UN);     // union: qw then agg
    float* agg_s = (float*)(smc + SB_UN);
    float* red   = (float*)(smc + SB_RED);
    float* rowm  = (float*)(smc + SB_ROWM);
    float* rows  = (float*)(smc + SB_ROWS);
    const uint32_t sb = s2u(smc);

    const int tid = threadIdx.x, wid = tid >> 5, lane = tid & 31;
    const int bh = blockIdx.y, h = bh & 15;
    const int l0 = blockIdx.x * 16;
    const float dh = decay[h];
    const int mat = lane >> 3, rr8 = lane & 7;
    const int r1 = lane >> 2, cb = (lane & 3) * 2;

    // Q tiles
    {
        const uint32_t* qh32 = (const uint32_t*)(Qhp + ((size_t)(bh << 10) + l0) * 64);
        const uint32_t* ql32 = (const uint32_t*)(Qlp + ((size_t)(bh << 10) + l0) * 64);
#pragma unroll
        for (int i = 0; i < 2; i++) {
            const int lin = tid + i * 256;
            const int row = lin >> 5, c2 = lin & 31;
            ((uint32_t*)(smc + SB_QH))[row * 36 + c2] = qh32[row * 32 + c2];
            ((uint32_t*)(smc + SB_QL))[row * 36 + c2] = ql32[row * 32 + c2];
        }
    }
    __syncthreads();

    // per-warp Q fragments
    uint32_t ah[4][4], al[4][4];
#pragma unroll
    for (int kk = 0; kk < 4; kk++) {
        const uint32_t addr = sb + SB_QH + (((lane & 15)) * 72 + kk * 16 + (lane >> 4) * 8) * 2;
        ldm4(ah[kk], addr);
        ldm4(al[kk], addr + (SB_QL - SB_QH));
    }

    // fused qrel: qw[16][257] via 5 chunks of 64 p-cols
    for (int rc = 0; rc < 5; rc++) {
        const int p0c = rc * 64;
        if (rc < 4) {
#pragma unroll
            for (int it = 0; it < 2; it++) {
                const int idx = tid + it * 256;
                const int row = idx >> 3, c8 = idx & 7;
                const uint32_t doff = (row * 72 + c8 * 8) * 2;
                cp16(sb + SB_KH + doff, rkh + (size_t)(p0c + row) * 64 + c8 * 8);
                cp16(sb + SB_KL + doff, rkl + (size_t)(p0c + row) * 64 + c8 * 8);
            }
            cp_commit_wait();
        } else {
            // tail: p=256 only; zero both tiles then load row 0
#pragma unroll
            for (int it = 0; it < 9; it++) {
                const int idx = tid + it * 256;
                ((uint32_t*)(smc + SB_KH))[idx] = 0u;
                ((uint32_t*)(smc + SB_KL))[idx] = 0u;
            }
            __syncthreads();
            if (tid < 32) {
                ((uint32_t*)(smc + SB_KH))[tid] = ((const uint32_t*)rkh)[256 * 32 + tid];
                ((uint32_t*)(smc + SB_KL))[tid] = ((const uint32_t*)rkl)[256 * 32 + tid];
            }
        }
        __syncthreads();

        float c[4] = {0.f, 0.f, 0.f, 0.f};
#pragma unroll
        for (int kk2 = 0; kk2 < 2; kk2++) {
            uint32_t kh4[4], kl4[4];
            const uint32_t addr = sb + SB_KH + ((wid * 8 + rr8) * 72 + kk2 * 32 + mat * 8) * 2;
            ldm4(kh4, addr);
            ldm4(kl4, addr + (SB_KL - SB_KH));
            mma16816(c, ah[2 * kk2], &kh4[0]);
            mma16816(c, ah[2 * kk2], &kl4[0]);
            mma16816(c, al[2 * kk2], &kh4[0]);
            mma16816(c, ah[2 * kk2 + 1], &kh4[2]);
            mma16816(c, ah[2 * kk2 + 1], &kl4[2]);
            mma16816(c, al[2 * kk2 + 1], &kh4[2]);
        }
        const int colb = p0c + wid * 8 + cb;
#pragma unroll
        for (int half = 0; half < 2; half++) {
            const int row = r1 + half * 8;
            if (colb < NREL)     qw[row * 264 + colb]     = c[half * 2 + 0];
            if (colb + 1 < NREL) qw[row * 264 + colb + 1] = c[half * 2 + 1];
        }
        __syncthreads();
    }

    // QK: 16 chunks of 64 keys
    for (int ch = 0; ch < 16; ch++) {
#pragma unroll
        for (int it = 0; it < 2; it++) {
            const int idx = tid + it * 256;
            const int row = idx >> 3, c8 = idx & 7;
            const uint32_t doff = (row * 72 + c8 * 8) * 2;
            const size_t src = ((size_t)(bh << 10) + ch * 64 + row) * 64 + c8 * 8;
            cp16(sb + SB_KH + doff, Khp + src);
            cp16(sb + SB_KL + doff, Klp + src);
        }
        cp_commit_wait();
        __syncthreads();

        float c[4] = {0.f, 0.f, 0.f, 0.f};
#pragma unroll
        for (int kk2 = 0; kk2 < 2; kk2++) {
            uint32_t kh4[4], kl4[4];
            const uint32_t addr = sb + SB_KH + ((wid * 8 + rr8) * 72 + kk2 * 32 + mat * 8) * 2;
            ldm4(kh4, addr);
            ldm4(kl4, addr + (SB_KL - SB_KH));
            mma16816(c, ah[2 * kk2], &kh4[0]);
            mma16816(c, ah[2 * kk2], &kl4[0]);
            mma16816(c, al[2 * kk2], &kh4[0]);
            mma16816(c, ah[2 * kk2 + 1], &kh4[2]);
            mma16816(c, ah[2 * kk2 + 1], &kl4[2]);
            mma16816(c, al[2 * kk2 + 1], &kh4[2]);
        }

        const int colb = ch * 64 + wid * 8 + cb;
#pragma unroll
        for (int half = 0; half < 2; half++) {
            const int row = r1 + half * 8;
            const int lg = l0 + row;
            const int rel0 = colb - lg;
            const int rel1 = rel0 + 1;
            const int rc0 = rel0 < -MAXREL ? -MAXREL : (rel0 > MAXREL ? MAXREL : rel0);
            const int rc1 = rel1 < -MAXREL ? -MAXREL : (rel1 > MAXREL ? MAXREL : rel1);
            float2 v;
            v.x = c[half * 2 + 0] * 0.125f + qw[row * 264 + rc0 + MAXREL]
                - dh * fabsf((float)rel0);
            v.y = c[half * 2 + 1] * 0.125f + qw[row * 264 + rc1 + MAXREL]
                - dh * fabsf((float)rel1);
            *(float2*)(sbuf + row * AT_PITCH + colb) = v;
        }
        __syncthreads();
    }

    // softmax
    const int row = tid >> 4, lane16 = tid & 15;
    float m = -3.0e38f;
    for (int j = 0; j < 64; j++) m = fmaxf(m, sbuf[row * AT_PITCH + lane16 + (j << 4)]);
    red[row * 16 + lane16] = m;
    __syncthreads();
    if (lane16 == 0) {
        float mm = red[row * 16];
        for (int j = 1; j < 16; j++) mm = fmaxf(mm, red[row * 16 + j]);
        rowm[row] = mm;
    }
    __syncthreads();
    const float mm = rowm[row];
    float sum = 0.f;
    for (int j = 0; j < 64; j++) {
        const int cidx = lane16 + (j << 4);
        const float e = __expf(sbuf[row * AT_PITCH + cidx] - mm);
        sbuf[row * AT_PITCH + cidx] = e;
        sum += e;
    }
    red[row * 16 + lane16] = sum;
    __syncthreads();
    if (lane16 == 0) {
        float ss = 0.f;
        for (int j = 0; j < 16; j++) ss += red[row * 16 + j];
        rows[row] = ss;
    }
    __syncthreads();

    // zero union (qw dead) for agg
#pragma unroll
    for (int i = 0; i < 17; i++) {
        const int idx = tid + i * 256;
        if (idx < 16 * 272) agg_s[idx] = 0.f;
    }
    __syncthreads();

    // bucket aggregation
    {
        const int lg = l0 + row;
        float c0 = 0.f, c1 = 0.f;
        for (int j = 0; j < 64; j++) {
            const int r = lane16 + (j << 4);
            const float e = sbuf[row * AT_PITCH + r];
            const int rel = r - lg;
            if (rel <= -MAXREL)      c0 += e;
            else if (rel >= MAXREL)  c1 += e;
            else                     agg_s[row * 272 + rel + MAXREL] = e;
        }
        atomicAdd(&agg_s[row * 272 + 0], c0);
        atomicAdd(&agg_s[row * 272 + 256], c1);
    }
    __syncthreads();

    // agg bf16 hi/lo write
#pragma unroll
    for (int k = 0; k < 16; k++) {
        const int i = tid + k * 256;
        const int r2 = i >> 8, p = i & 255;
        const float val = agg_s[r2 * 272 + p] * (1.0f / rows[r2]);
        const size_t off = ((size_t)(bh << 10) + l0 + r2) * 272 + p;
        __nv_bfloat16 hh = __float2bfloat16(val);
        agh[off] = hh;
        agl[off] = __float2bfloat16(val - __bfloat162float(hh));
    }
    {
        const int r2 = tid >> 4, p = 256 + (tid & 15);
        const float val = agg_s[r2 * 272 + p] * (1.0f / rows[r2]);
        const size_t off = ((size_t)(bh << 10) + l0 + r2) * 272 + p;
        __nv_bfloat16 hh = __float2bfloat16(val);
        agh[off] = hh;
        agl[off] = __float2bfloat16(val - __bfloat162float(hh));
    }

    // normalized attn write (float4)
    for (int l = 0; l < 16; l++) {
        const float inv = 1.0f / rows[l];
        float4 v = *(const float4*)(sbuf + l * AT_PITCH + tid * 4);
        v.x *= inv; v.y *= inv; v.z *= inv; v.w *= inv;
        *(float4*)(attn + (((size_t)(bh << 10) + l0 + l) << 10) + tid * 4) = v;
    }
}

// ---------------- ctx: split-bf16 mma (R12, unchanged) ----------------
#define CP   136
#define CPB  (CP*2)
#define RVP  136
#define C_AH 0
#define C_AL (128*CPB)
#define C_VH (2*128*CPB)
#define C_VL (C_VH + 128*72*2)
#define CTX_SMEM (C_VL + 128*72*2)

__global__ __launch_bounds__(256, 2) void ctx_mma(const float* __restrict__ attn,
                                                  const __nv_bfloat16* __restrict__ Vh,
                                                  const __nv_bfloat16* __restrict__ Vl,
                                                  const __nv_bfloat16* __restrict__ agh,
                                                  const __nv_bfloat16* __restrict__ agl,
                                                  const float* __restrict__ relv,
                                                  float* __restrict__ ctx) {
    extern __shared__ char smc[];
    const uint32_t sb = s2u(smc);
    const int tid = threadIdx.x, wid = tid >> 5, lane = tid & 31;
    const int bh = blockIdx.y, b = bh >> 4, h = bh & 15;
    const int l0 = blockIdx.x * 128;
    const int wm = wid >> 1, wn = wid & 1;

    float c[2][4][4];
#pragma unroll
    for (int i = 0; i < 2; i++)
#pragma unroll
        for (int j = 0; j < 4; j++)
#pragma unroll
            for (int q = 0; q < 4; q++) c[i][j][q] = 0.f;

    for (int ck = 0; ck < 11; ck++) {
        const int KS = (ck == 10) ? 1 : 8;
        __syncthreads();
        if (ck < 8) {
#pragma unroll
            for (int it = 0; it < 16; it++) {
                const int idx = tid + it * 256;
                const int row = idx >> 5, c4 = idx & 31;
                const float4 v = *(const float4*)(attn +
                    (((size_t)(bh << 10) + l0 + row) << 10) + ck * 128 + c4 * 4);
                *(uint2*)(smc + C_AH + row * CPB + c4 * 8) =
                    make_uint2(pack_hi(v.x, v.y), pack_hi(v.z, v.w));
                *(uint2*)(smc + C_AL + row * CPB + c4 * 8) =
                    make_uint2(pack_lo(v.x, v.y), pack_lo(v.z, v.w));
            }
#pragma unroll
            for (int it = 0; it < 4; it++) {
                const int idx = tid + it * 256;
                const int row = idx >> 3, j = idx & 7;
                const size_t src = ((size_t)(bh << 10) + ck * 128 + row) * 64 + j * 8;
                *(uint4*)(smc + C_VH + row * 144 + j * 16) = *(const uint4*)((const char*)Vh + src * 2);
                *(uint4*)(smc + C_VL + row * 144 + j * 16) = *(const uint4*)((const char*)Vl + src * 2);
            }
        } else if (ck < 10) {
            const int p0 = (ck - 8) * 128;
#pragma unroll
            for (int it = 0; it < 8; it++) {
                const int idx = tid + it * 256;
                const int row = idx >> 4, j = idx & 15;
                const size_t src = ((size_t)(bh << 10) + l0 + row) * 272 + p0 + j * 8;
                *(uint4*)(smc + C_AH + row * CPB + j * 16) = *(const uint4*)((const char*)agh + src * 2);
                *(uint4*)(smc + C_AL + row * CPB + j * 16) = *(const uint4*)((const char*)agl + src * 2);
            }
#pragma unroll
            for (int it = 0; it < 32; it++) {
                const int idx = tid + it * 256;
                const int d = idx >> 7, p = idx & 127;
                const float v = relv[(size_t)(p0 + p) * 64 + d];
                __nv_bfloat16 hh = __float2bfloat16(v);
                *(__nv_bfloat16*)(smc + C_VH + (d * RVP + p) * 2) = hh;
                *(__nv_bfloat16*)(smc + C_VL + (d * RVP + p) * 2) =
                    __float2bfloat16(v - __bfloat162float(hh));
            }
        } else {
            const int row = tid >> 1, j = tid & 1;
            const size_t src = ((size_t)(bh << 10) + l0 + row) * 272 + 256 + j * 8;
            *(uint4*)(smc + C_AH + row * CPB + j * 16) = *(const uint4*)((const char*)agh + src * 2);
            *(uint4*)(smc + C_AL + row * CPB + j * 16) = *(const uint4*)((const char*)agl + src * 2);
#pragma unroll
            for (int it = 0; it < 2; it++) {
                const int idx = tid + it * 256;
                const int d = idx >> 3, jj = idx & 7;
                ((uint32_t*)(smc + C_VH))[d * (RVP / 2) + jj] = 0u;
                ((uint32_t*)(smc + C_VL))[d * (RVP / 2) + jj] = 0u;
            }
            __syncthreads();
            if (tid < 64) {
                const float v = relv[(size_t)256 * 64 + tid];
                __nv_bfloat16 hh = __float2bfloat16(v);
                *(__nv_bfloat16*)(smc + C_VH + (tid * RVP) * 2) = hh;
                *(__nv_bfloat16*)(smc + C_VL + (tid * RVP) * 2) =
                    __float2bfloat16(v - __bfloat162float(hh));
            }
        }
        __syncthreads();

        for (int kk = 0; kk < KS; kk++) {
            uint32_t a_h[2][4], a_l[2][4];
#pragma unroll
            for (int i = 0; i < 2; i++) {
                const uint32_t addr = sb + C_AH +
                    ((wm * 32 + i * 16 + (lane & 15)) * CP + kk * 16 + (lane >> 4) * 8) * 2;
                ldm4(a_h[i], addr);
                ldm4(a_l[i], addr + (C_AL - C_AH));
            }
            uint32_t b_h[2][4], b_l[2][4];
            const int mat = lane >> 3, rr8 = lane & 7;
            if (ck < 8) {
#pragma unroll
                for (int nb = 0; nb < 2; nb++) {
                    const uint32_t addr = sb + C_VH +
                        ((kk * 16 + (mat & 1) * 8 + rr8) * 72 + wn * 32 + nb * 16 + (mat >> 1) * 8) * 2;
                    ldm4t(b_h[nb], addr);
                    ldm4t(b_l[nb], addr + (C_VL - C_VH));
                }
            } else {
#pragma unroll
                for (int nb = 0; nb < 2; nb++) {
                    const uint32_t addr = sb + C_VH +
                        ((wn * 32 + nb * 16 + (mat >> 1) * 8 + rr8) * RVP + kk * 16 + (mat & 1) * 8) * 2;
                    ldm4(b_h[nb], addr);
                    ldm4(b_l[nb], addr + (C_VL - C_VH));
                }
            }
#pragma unroll
            for (int i = 0; i < 2; i++)
#pragma unroll
                for (int nb = 0; nb < 2; nb++)
#pragma unroll
                    for (int half = 0; half < 2; half++) {
                        const int j = nb * 2 + half;
                        mma16816(c[i][j], a_h[i], &b_h[nb][half * 2]);
                        mma16816(c[i][j], a_h[i], &b_l[nb][half * 2]);
                        mma16816(c[i][j], a_l[i], &b_h[nb][half * 2]);
                    }
        }
    }

    const int rr = lane >> 2, cc = (lane & 3) * 2;
#pragma unroll
    for (int i = 0; i < 2; i++)
#pragma unroll
        for (int j = 0; j < 4; j++)
#pragma unroll
            for (int half = 0; half < 2; half++) {
                const int m = l0 + wm * 32 + i * 16 + rr + half * 8;
                const int d = wn * 32 + j * 8 + cc;
                float2 v;
                v.x = c[i][j][half * 2 + 0];
                v.y = c[i][j][half * 2 + 1];
                *(float2*)(ctx + ((size_t)(b << 10) + m) * 1024 + h * 64 + d) = v;
            }
}

// ---------------------------------------------------------------------------
extern "C" void kernel_launch(void* const* d_in, const int* in_sizes, int n_in,
                              void* d_out, int out_size) {
    const float* query = (const float*)d_in[0];
    const float* key_  = (const float*)d_in[1];
    const float* value = (const float*)d_in[2];
    const float* w_q   = (const float*)d_in[3];
    const float* w_k   = (const float*)d_in[4];
    const float* w_v   = (const float*)d_in[5];
    const float* w_o   = (const float*)d_in[6];
    const float* b_o   = (const float*)d_in[7];
    const float* rel_k = (const float*)d_in[8];
    const float* rel_v = (const float*)d_in[9];
    const float* decay = (const float*)d_in[10];

    float* out  = (float*)d_out;
    float* attn = out + (size_t)MTOT * DMODEL;

    float *ctx;
    __nv_bfloat16 *Ah, *Al, *Wh, *Wl, *Qh, *Ql, *Kh, *Kl, *Vh, *Vl, *rkh, *rkl, *agh, *agl;
    cudaGetSymbolAddress((void**)&ctx,  g_ctx);
    cudaGetSymbolAddress((void**)&Ah,   g_Ah);
    cudaGetSymbolAddress((void**)&Al,   g_Al);
    cudaGetSymbolAddress((void**)&Wh,   g_Wh);
    cudaGetSymbolAddress((void**)&Wl,   g_Wl);
    cudaGetSymbolAddress((void**)&Qh,   g_Qh);
    cudaGetSymbolAddress((void**)&Ql,   g_Ql);
    cudaGetSymbolAddress((void**)&Kh,   g_Kh);
    cudaGetSymbolAddress((void**)&Kl,   g_Kl);
    cudaGetSymbolAddress((void**)&Vh,   g_Vh);
    cudaGetSymbolAddress((void**)&Vl,   g_Vl);
    cudaGetSymbolAddress((void**)&rkh,  g_rkh);
    cudaGetSymbolAddress((void**)&rkl,  g_rkl);
    cudaGetSymbolAddress((void**)&agh,  g_agh);
    cudaGetSymbolAddress((void**)&agl,  g_agl);

    cudaFuncSetAttribute(gemm_mma<0>, cudaFuncAttributeMaxDynamicSharedMemorySize, GEMM_SMEM);
    cudaFuncSetAttribute(gemm_mma<1>, cudaFuncAttributeMaxDynamicSharedMemorySize, GEMM_SMEM);
    cudaFuncSetAttribute(attn_kernel, cudaFuncAttributeMaxDynamicSharedMemorySize, ATTN_SMEM_BYTES);
    cudaFuncSetAttribute(ctx_mma, cudaFuncAttributeMaxDynamicSharedMemorySize, CTX_SMEM);

    const int nA4 = MTOT * DMODEL / 4;
    const int nW4 = DMODEL * DMODEL / 4;
    const int nR4 = NREL * DK / 4;
    const dim3 ggemm(DMODEL / 128, MTOT / 128);

    cvt_split<<<nA4 / 256, 256>>>((const float4*)query, (uint2*)Ah, (uint2*)Al, nA4);
    cvt_split<<<nW4 / 256, 256>>>((const float4*)w_q, (uint2*)Wh, (uint2*)Wl, nW4);
    gemm_mma<0><<<ggemm, 256, GEMM_SMEM>>>(Ah, Al, Wh, Wl, nullptr, nullptr, Qh, Ql);

    cvt_split<<<nA4 / 256, 256>>>((const float4*)key_, (uint2*)Ah, (uint2*)Al, nA4);
    cvt_split<<<nW4 / 256, 256>>>((const float4*)w_k, (uint2*)Wh, (uint2*)Wl, nW4);
    gemm_mma<0><<<ggemm, 256, GEMM_SMEM>>>(Ah, Al, Wh, Wl, nullptr, nullptr, Kh, Kl);

    cvt_split<<<nA4 / 256, 256>>>((const float4*)value, (uint2*)Ah, (uint2*)Al, nA4);
    cvt_split<<<nW4 / 256, 256>>>((const float4*)w_v, (uint2*)Wh, (uint2*)Wl, nW4);
    gemm_mma<0><<<ggemm, 256, GEMM_SMEM>>>(Ah, Al, Wh, Wl, nullptr, nullptr, Vh, Vl);

    cvt_split<<<(nR4 + 255) / 256, 256>>>((const float4*)rel_k, (uint2*)rkh, (uint2*)rkl, nR4);

    attn_kernel<<<dim3(SEQ / 16, BH), 256, ATTN_SMEM_BYTES>>>(Qh, Ql, Kh, Kl, rkh, rkl,
                                                              decay, attn, agh, agl);

    ctx_mma<<<dim3(SEQ / 128, BH), 256, CTX_SMEM>>>(attn, Vh, Vl, agh, agl, rel_v, ctx);

    cvt_split<<<nA4 / 256, 256>>>((const float4*)ctx, (uint2*)Ah, (uint2*)Al, nA4);
    cvt_split<<<nW4 / 256, 256>>>((const float4*)w_o, (uint2*)Wh, (uint2*)Wl, nW4);
    gemm_mma<1><<<ggemm, 256, GEMM_SMEM>>>(Ah, Al, Wh, Wl, b_o, out, nullptr, nullptr);
}

// round 14
// speedup vs baseline: 2.0143x; 1.0390x over previous
#include <cuda_runtime.h>
#include <cuda_bf16.h>
#include <math.h>
#include <stdint.h>

#define BATCH 8
#define SEQ   1024
#define DMODEL 1024
#define NHEADS 16
#define DK    64
#define NREL  257
#define MAXREL 128
#define MTOT  (BATCH*SEQ)
#define BH    (BATCH*NHEADS)

__device__ __nv_bfloat16 g_Ah[MTOT*DMODEL];
__device__ __nv_bfloat16 g_Al[MTOT*DMODEL];
__device__ __nv_bfloat16 g_Wh[DMODEL*DMODEL];
__device__ __nv_bfloat16 g_Wl[DMODEL*DMODEL];
__device__ __nv_bfloat16 g_Qh[BH*SEQ*DK];
__device__ __nv_bfloat16 g_Ql[BH*SEQ*DK];
__device__ __nv_bfloat16 g_Kh[BH*SEQ*DK];
__device__ __nv_bfloat16 g_Kl[BH*SEQ*DK];
__device__ __nv_bfloat16 g_Vh[BH*SEQ*DK];
__device__ __nv_bfloat16 g_Vl[BH*SEQ*DK];
__device__ __nv_bfloat16 g_rkh[NREL*DK + 64];
__device__ __nv_bfloat16 g_rkl[NREL*DK + 64];
__device__ __nv_bfloat16 g_agh[(size_t)BH*SEQ*272];
__device__ __nv_bfloat16 g_agl[(size_t)BH*SEQ*272];

// ---------------- helpers ----------------
__device__ __forceinline__ uint32_t s2u(const void* p) {
    uint32_t a;
    asm("{ .reg .u64 t; cvta.to.shared.u64 t, %1; cvt.u32.u64 %0, t; }" : "=r"(a) : "l"(p));
    return a;
}
__device__ __forceinline__ void cp16(uint32_t dst, const void* src) {
    asm volatile("cp.async.cg.shared.global [%0], [%1], 16;" :: "r"(dst), "l"(src) : "memory");
}
__device__ __forceinline__ void cp_commit() {
    asm volatile("cp.async.commit_group;" ::: "memory");
}
__device__ __forceinline__ void cp_wait0() {
    asm volatile("cp.async.wait_group 0;" ::: "memory");
}
__device__ __forceinline__ void ldm4(uint32_t* r, uint32_t addr) {
    asm volatile("ldmatrix.sync.aligned.m8n8.x4.shared.b16 {%0,%1,%2,%3}, [%4];"
                 : "=r"(r[0]), "=r"(r[1]), "=r"(r[2]), "=r"(r[3]) : "r"(addr));
}
__device__ __forceinline__ void ldm4t(uint32_t* r, uint32_t addr) {
    asm volatile("ldmatrix.sync.aligned.m8n8.x4.trans.shared.b16 {%0,%1,%2,%3}, [%4];"
                 : "=r"(r[0]), "=r"(r[1]), "=r"(r[2]), "=r"(r[3]) : "r"(addr));
}
__device__ __forceinline__ void mma16816(float* d, const uint32_t* a, const uint32_t* b) {
    asm volatile(
        "mma.sync.aligned.m16n8k16.row.col.f32.bf16.bf16.f32 "
        "{%0,%1,%2,%3}, {%4,%5,%6,%7}, {%8,%9}, {%0,%1,%2,%3};"
        : "+f"(d[0]), "+f"(d[1]), "+f"(d[2]), "+f"(d[3])
        : "r"(a[0]), "r"(a[1]), "r"(a[2]), "r"(a[3]), "r"(b[0]), "r"(b[1]));
}
__device__ __forceinline__ uint32_t pack_hi(float a, float b) {
    __nv_bfloat16 h0 = __float2bfloat16(a), h1 = __float2bfloat16(b);
    return (uint32_t)__bfloat16_as_ushort(h0) | ((uint32_t)__bfloat16_as_ushort(h1) << 16);
}
__device__ __forceinline__ uint32_t pack_lo(float a, float b) {
    __nv_bfloat16 h0 = __float2bfloat16(a), h1 = __float2bfloat16(b);
    __nv_bfloat16 l0 = __float2bfloat16(a - __bfloat162float(h0));
    __nv_bfloat16 l1 = __float2bfloat16(b - __bfloat162float(h1));
    return (uint32_t)__bfloat16_as_ushort(l0) | ((uint32_t)__bfloat16_as_ushort(l1) << 16);
}

// ---------------- fp32 -> bf16 hi/lo split (guarded) ----------------
__global__ __launch_bounds__(256) void cvt_split(const float4* __restrict__ x,
                                                 uint2* __restrict__ hi,
                                                 uint2* __restrict__ lo,
                                                 int n4) {
    const int i = blockIdx.x * 256 + threadIdx.x;
    if (i >= n4) return;
    const float4 v = x[i];
    uint2 H, L;
    H.x = pack_hi(v.x, v.y); H.y = pack_hi(v.z, v.w);
    L.x = pack_lo(v.x, v.y); L.y = pack_lo(v.z, v.w);
    hi[i] = H;
    lo[i] = L;
}

// ---------------- mma.sync bf16 split GEMM (R12, unchanged) ----------------
#define PITCH 72
#define MATB (128*PITCH*2)
#define STAGEB (4*MATB)
#define GEMM_SMEM (2*STAGEB)

template<int MODE>
__global__ __launch_bounds__(256, 1) void gemm_mma(const __nv_bfloat16* __restrict__ Ah,
                                                   const __nv_bfloat16* __restrict__ Al,
                                                   const __nv_bfloat16* __restrict__ Wh,
                                                   const __nv_bfloat16* __restrict__ Wl,
                                                   const float* __restrict__ bias,
                                                   float* __restrict__ out,
                                                   __nv_bfloat16* __restrict__ sh,
                                                   __nv_bfloat16* __restrict__ sl) {
    extern __shared__ char smc[];
    const uint32_t sb = s2u(smc);
    const int tid = threadIdx.x, wid = tid >> 5, lane = tid & 31;
    const int m0 = blockIdx.y * 128, n0 = blockIdx.x * 128;
    const int wm = wid >> 2, wn = wid & 3;

    float acc[4][4][4];
#pragma unroll
    for (int i = 0; i < 4; i++)
#pragma unroll
        for (int j = 0; j < 4; j++)
#pragma unroll
            for (int q = 0; q < 4; q++) acc[i][j][q] = 0.f;

    auto issue = [&](int s) {
        const uint32_t bu = sb + (s & 1) * STAGEB;
        const int k0 = s * 64;
#pragma unroll
        for (int it = 0; it < 4; it++) {
            const int idx = tid + it * 256;
            const int row = idx >> 3, j = idx & 7;
            const uint32_t doff = row * (PITCH * 2) + j * 16;
            const size_t ga = ((size_t)(m0 + row) * 1024 + k0 + j * 8) * 2;
            const size_t gw = ((size_t)(n0 + row) * 1024 + k0 + j * 8) * 2;
            cp16(bu + 0 * MATB + doff, (const char*)Ah + ga);
            cp16(bu + 1 * MATB + doff, (const char*)Al + ga);
            cp16(bu + 2 * MATB + doff, (const char*)Wh + gw);
            cp16(bu + 3 * MATB + doff, (const char*)Wl + gw);
        }
        cp_commit();
    };

    issue(0);
    for (int s = 0; s < 16; s++) {
        if (s + 1 < 16) {
            issue(s + 1);
            asm volatile("cp.async.wait_group 1;" ::: "memory");
        } else {
            cp_wait0();
        }
        __syncthreads();
        const uint32_t bu = sb + (s & 1) * STAGEB;
#pragma unroll
        for (int kk = 0; kk < 4; kk++) {
            const int k16 = kk * 16;
            uint32_t ah[4][4], al[4][4];
#pragma unroll
            for (int i = 0; i < 4; i++) {
                const uint32_t addr = bu +
                    ((wm * 64 + i * 16 + (lane & 15)) * PITCH + k16 + (lane >> 4) * 8) * 2;
                ldm4(ah[i], addr);
                ldm4(al[i], addr + MATB);
            }
            uint32_t wh[2][4], wl[2][4];
#pragma unroll
            for (int j = 0; j < 2; j++) {
                const int mat = lane >> 3, rr = lane & 7;
                const int n = wn * 32 + j * 16 + (mat >> 1) * 8 + rr;
                const int k = k16 + (mat & 1) * 8;
                const uint32_t addr = bu + 2 * MATB + (n * PITCH + k) * 2;
                ldm4(wh[j], addr);
                ldm4(wl[j], addr + MATB);
            }
#pragma unroll
            for (int i = 0; i < 4; i++)
#pragma unroll
                for (int nt = 0; nt < 4; nt++) {
                    const uint32_t* bhf = &wh[nt >> 1][(nt & 1) * 2];
                    const uint32_t* blf = &wl[nt >> 1][(nt & 1) * 2];
                    mma16816(acc[i][nt], ah[i], bhf);
                    mma16816(acc[i][nt], ah[i], blf);
                    mma16816(acc[i][nt], al[i], bhf);
                }
        }
        __syncthreads();
    }

    const int rr = lane >> 2, cc = (lane & 3) * 2;
#pragma unroll
    for (int i = 0; i < 4; i++) {
#pragma unroll
        for (int nt = 0; nt < 4; nt++) {
            const int n = n0 + wn * 32 + nt * 8 + cc;
#pragma unroll
            for (int half = 0; half < 2; half++) {
                const int m = m0 + wm * 64 + i * 16 + rr + half * 8;
                float2 v;
                v.x = acc[i][nt][half * 2 + 0];
                v.y = acc[i][nt][half * 2 + 1];
                if (MODE == 0) {
                    const int b = m >> 10, sI = m & 1023, h = n >> 6, dd = n & 63;
                    const size_t off = (((size_t)(b * NHEADS + h) << 10) + sI) * 64 + dd;
                    *(uint32_t*)(sh + off) = pack_hi(v.x, v.y);
                    *(uint32_t*)(sl + off) = pack_lo(v.x, v.y);
                } else {
                    v.x += bias[n];
                    v.y += bias[n + 1];
                    *(float2*)(out + (size_t)m * 1024 + n) = v;
                }
            }
        }
    }
}

// ---------------- attn: pipelined 64-key chunks, 2 CTAs/SM ----------------
#define AT_PITCH 1032
#define SB_SBUF 0
#define SB_QH   (16*AT_PITCH*4)
#define SB_QL   (SB_QH + 2304)
#define SB_KH   (SB_QL + 2304)
#define SB_KL   (SB_KH + 64*72*2)
#define SB_UN   (SB_KL + 64*72*2)
#define SB_RED  (SB_UN + 16*272*4)
#define SB_ROWM (SB_RED + 1024)
#define SB_ROWS (SB_ROWM + 64)
#define ATTN_SMEM_BYTES (SB_ROWS + 64)        // 107648 -> 2 CTAs/SM

__global__ __launch_bounds__(256, 2) void attn_kernel(const __nv_bfloat16* __restrict__ Qhp,
                                                      const __nv_bfloat16* __restrict__ Qlp,
                                                      const __nv_bfloat16* __restrict__ Khp,
                                                      const __nv_bfloat16* __restrict__ Klp,
                                                      const __nv_bfloat16* __restrict__ rkh,
                                                      const __nv_bfloat16* __restrict__ rkl,
                                                      const float* __restrict__ decay,
                                                      float* __restrict__ attn,
                                                      __nv_bfloat16* __restrict__ agh,
                                                      __nv_bfloat16* __restrict__ agl) {
    extern __shared__ char smc[];
    float* sbuf  = (float*)(smc + SB_SBUF);
    float* qw    = (float*)(smc + SB_UN);
    float* agg_s = (float*)(smc + SB_UN);
    float* red   = (float*)(smc + SB_RED);
    float* rowm  = (float*)(smc + SB_ROWM);
    float* rows  = (float*)(smc + SB_ROWS);
    const uint32_t sb = s2u(smc);

    const int tid = threadIdx.x, wid = tid >> 5, lane = tid & 31;
    const int bh = blockIdx.y, h = bh & 15;
    const int l0 = blockIdx.x * 16;
    const float dh = decay[h];
    const int mat = lane >> 3, rr8 = lane & 7;
    const int r1 = lane >> 2, cb = (lane & 3) * 2;

    // Q tiles
    {
        const uint32_t* qh32 = (const uint32_t*)(Qhp + ((size_t)(bh << 10) + l0) * 64);
        const uint32_t* ql32 = (const uint32_t*)(Qlp + ((size_t)(bh << 10) + l0) * 64);
#pragma unroll
        for (int i = 0; i < 2; i++) {
            const int lin = tid + i * 256;
            const int row = lin >> 5, c2 = lin & 31;
            ((uint32_t*)(smc + SB_QH))[row * 36 + c2] = qh32[row * 32 + c2];
            ((uint32_t*)(smc + SB_QL))[row * 36 + c2] = ql32[row * 32 + c2];
        }
    }
    __syncthreads();

    uint32_t ah[4][4], al[4][4];
#pragma unroll
    for (int kk = 0; kk < 4; kk++) {
        const uint32_t addr = sb + SB_QH + (((lane & 15)) * 72 + kk * 16 + (lane >> 4) * 8) * 2;
        ldm4(ah[kk], addr);
        ldm4(al[kk], addr + (SB_QL - SB_QH));
    }

    auto issue_rk = [&](int rc) {
#pragma unroll
        for (int it = 0; it < 2; it++) {
            const int idx = tid + it * 256;
            const int row = idx >> 3, c8 = idx & 7;
            const uint32_t doff = (row * 72 + c8 * 8) * 2;
            cp16(sb + SB_KH + doff, rkh + (size_t)(rc * 64 + row) * 64 + c8 * 8);
            cp16(sb + SB_KL + doff, rkl + (size_t)(rc * 64 + row) * 64 + c8 * 8);
        }
        cp_commit();
    };
    auto issue_k = [&](int ch) {
#pragma unroll
        for (int it = 0; it < 2; it++) {
            const int idx = tid + it * 256;
            const int row = idx >> 3, c8 = idx & 7;
            const uint32_t doff = (row * 72 + c8 * 8) * 2;
            const size_t src = ((size_t)(bh << 10) + ch * 64 + row) * 64 + c8 * 8;
            cp16(sb + SB_KH + doff, Khp + src);
            cp16(sb + SB_KL + doff, Klp + src);
        }
        cp_commit();
    };

    // fused qrel (pipelined): qw[16][257] via 5 chunks of 64 p-cols
    issue_rk(0);
    for (int rc = 0; rc < 5; rc++) {
        if (rc < 4) {
            cp_wait0();
            __syncthreads();
        } else {
            // tail: p=256; buffer free (prev ldm synced)
#pragma unroll
            for (int it = 0; it < 9; it++) {
                const int idx = tid + it * 256;
                ((uint32_t*)(smc + SB_KH))[idx] = 0u;
                ((uint32_t*)(smc + SB_KL))[idx] = 0u;
            }
            __syncthreads();
            if (tid < 32) {
                ((uint32_t*)(smc + SB_KH))[tid] = ((const uint32_t*)rkh)[256 * 32 + tid];
                ((uint32_t*)(smc + SB_KL))[tid] = ((const uint32_t*)rkl)[256 * 32 + tid];
            }
            __syncthreads();
        }
        // fragments
        uint32_t kh4[2][4], kl4[2][4];
#pragma unroll
        for (int kk2 = 0; kk2 < 2; kk2++) {
            const uint32_t addr = sb + SB_KH + ((wid * 8 + rr8) * 72 + kk2 * 32 + mat * 8) * 2;
            ldm4(kh4[kk2], addr);
            ldm4(kl4[kk2], addr + (SB_KL - SB_KH));
        }
        __syncthreads();
        if (rc < 3) issue_rk(rc + 1);
        // compute
        float c[4] = {0.f, 0.f, 0.f, 0.f};
#pragma unroll
        for (int kk2 = 0; kk2 < 2; kk2++) {
            mma16816(c, ah[2 * kk2], &kh4[kk2][0]);
            mma16816(c, ah[2 * kk2], &kl4[kk2][0]);
            mma16816(c, al[2 * kk2], &kh4[kk2][0]);
            mma16816(c, ah[2 * kk2 + 1], &kh4[kk2][2]);
            mma16816(c, ah[2 * kk2 + 1], &kl4[kk2][2]);
            mma16816(c, al[2 * kk2 + 1], &kh4[kk2][2]);
        }
        const int colb = rc * 64 + wid * 8 + cb;
#pragma unroll
        for (int half = 0; half < 2; half++) {
            const int row = r1 + half * 8;
            if (colb < NREL)     qw[row * 264 + colb]     = c[half * 2 + 0];
            if (colb + 1 < NREL) qw[row * 264 + colb + 1] = c[half * 2 + 1];
        }
    }
    __syncthreads();

    // QK: 16 pipelined chunks of 64 keys
    issue_k(0);
    for (int ch = 0; ch < 16; ch++) {
        cp_wait0();
        __syncthreads();
        uint32_t kh4[2][4], kl4[2][4];
#pragma unroll
        for (int kk2 = 0; kk2 < 2; kk2++) {
            const uint32_t addr = sb + SB_KH + ((wid * 8 + rr8) * 72 + kk2 * 32 + mat * 8) * 2;
            ldm4(kh4[kk2], addr);
            ldm4(kl4[kk2], addr + (SB_KL - SB_KH));
        }
        __syncthreads();
        if (ch + 1 < 16) issue_k(ch + 1);

        float c[4] = {0.f, 0.f, 0.f, 0.f};
#pragma unroll
        for (int kk2 = 0; kk2 < 2; kk2++) {
            mma16816(c, ah[2 * kk2], &kh4[kk2][0]);
            mma16816(c, ah[2 * kk2], &kl4[kk2][0]);
            mma16816(c, al[2 * kk2], &kh4[kk2][0]);
            mma16816(c, ah[2 * kk2 + 1], &kh4[kk2][2]);
            mma16816(c, ah[2 * kk2 + 1], &kl4[kk2][2]);
            mma16816(c, al[2 * kk2 + 1], &kh4[kk2][2]);
        }

        const int colb = ch * 64 + wid * 8 + cb;
#pragma unroll
        for (int half = 0; half < 2; half++) {
            const int row = r1 + half * 8;
            const int lg = l0 + row;
            const int rel0 = colb - lg;
            const int rel1 = rel0 + 1;
            const int rc0 = rel0 < -MAXREL ? -MAXREL : (rel0 > MAXREL ? MAXREL : rel0);
            const int rc1 = rel1 < -MAXREL ? -MAXREL : (rel1 > MAXREL ? MAXREL : rel1);
            float2 v;
            v.x = c[half * 2 + 0] * 0.125f + qw[row * 264 + rc0 + MAXREL]
                - dh * fabsf((float)rel0);
            v.y = c[half * 2 + 1] * 0.125f + qw[row * 264 + rc1 + MAXREL]
                - dh * fabsf((float)rel1);
            *(float2*)(sbuf + row * AT_PITCH + colb) = v;
        }
    }
    __syncthreads();

    // softmax
    const int row = tid >> 4, lane16 = tid & 15;
    float m = -3.0e38f;
    for (int j = 0; j < 64; j++) m = fmaxf(m, sbuf[row * AT_PITCH + lane16 + (j << 4)]);
    red[row * 16 + lane16] = m;
    __syncthreads();
    if (lane16 == 0) {
        float mm = red[row * 16];
        for (int j = 1; j < 16; j++) mm = fmaxf(mm, red[row * 16 + j]);
        rowm[row] = mm;
    }
    __syncthreads();
    const float mm = rowm[row];
    float sum = 0.f;
    for (int j = 0; j < 64; j++) {
        const int cidx = lane16 + (j << 4);
        const float e = __expf(sbuf[row * AT_PITCH + cidx] - mm);
        sbuf[row * AT_PITCH + cidx] = e;
        sum += e;
    }
    red[row * 16 + lane16] = sum;
    __syncthreads();
    if (lane16 == 0) {
        float ss = 0.f;
        for (int j = 0; j < 16; j++) ss += red[row * 16 + j];
        rows[row] = ss;
    }
    __syncthreads();

    // zero union (qw dead) for agg
#pragma unroll
    for (int i = 0; i < 17; i++) {
        const int idx = tid + i * 256;
        if (idx < 16 * 272) agg_s[idx] = 0.f;
    }
    __syncthreads();

    // bucket aggregation
    {
        const int lg = l0 + row;
        float c0 = 0.f, c1 = 0.f;
        for (int j = 0; j < 64; j++) {
            const int r = lane16 + (j << 4);
            const float e = sbuf[row * AT_PITCH + r];
            const int rel = r - lg;
            if (rel <= -MAXREL)      c0 += e;
            else if (rel >= MAXREL)  c1 += e;
            else                     agg_s[row * 272 + rel + MAXREL] = e;
        }
        atomicAdd(&agg_s[row * 272 + 0], c0);
        atomicAdd(&agg_s[row * 272 + 256], c1);
    }
    __syncthreads();

    // agg bf16 hi/lo write
#pragma unroll
    for (int k = 0; k < 16; k++) {
        const int i = tid + k * 256;
        const int r2 = i >> 8, p = i & 255;
        const float val = agg_s[r2 * 272 + p] * (1.0f / rows[r2]);
        const size_t off = ((size_t)(bh << 10) + l0 + r2) * 272 + p;
        __nv_bfloat16 hh = __float2bfloat16(val);
        agh[off] = hh;
        agl[off] = __float2bfloat16(val - __bfloat162float(hh));
    }
    {
        const int r2 = tid >> 4, p = 256 + (tid & 15);
        const float val = agg_s[r2 * 272 + p] * (1.0f / rows[r2]);
        const size_t off = ((size_t)(bh << 10) + l0 + r2) * 272 + p;
        __nv_bfloat16 hh = __float2bfloat16(val);
        agh[off] = hh;
        agl[off] = __float2bfloat16(val - __bfloat162float(hh));
    }

    // normalized attn write (float4)
    for (int l = 0; l < 16; l++) {
        const float inv = 1.0f / rows[l];
        float4 v = *(const float4*)(sbuf + l * AT_PITCH + tid * 4);
        v.x *= inv; v.y *= inv; v.z *= inv; v.w *= inv;
        *(float4*)(attn + (((size_t)(bh << 10) + l0 + l) << 10) + tid * 4) = v;
    }
}

// ---------------- ctx: split-bf16 mma, direct hi/lo output ----------------
#define CP   136
#define CPB  (CP*2)
#define RVP  136
#define C_AH 0
#define C_AL (128*CPB)
#define C_VH (2*128*CPB)
#define C_VL (C_VH + 128*72*2)
#define CTX_SMEM (C_VL + 128*72*2)

__global__ __launch_bounds__(256, 2) void ctx_mma(const float* __restrict__ attn,
                                                  const __nv_bfloat16* __restrict__ Vh,
                                                  const __nv_bfloat16* __restrict__ Vl,
                                                  const __nv_bfloat16* __restrict__ agh,
                                                  const __nv_bfloat16* __restrict__ agl,
                                                  const float* __restrict__ relv,
                                                  __nv_bfloat16* __restrict__ oh,
                                                  __nv_bfloat16* __restrict__ ol) {
    extern __shared__ char smc[];
    const uint32_t sb = s2u(smc);
    const int tid = threadIdx.x, wid = tid >> 5, lane = tid & 31;
    const int bh = blockIdx.y, b = bh >> 4, h = bh & 15;
    const int l0 = blockIdx.x * 128;
    const int wm = wid >> 1, wn = wid & 1;

    float c[2][4][4];
#pragma unroll
    for (int i = 0; i < 2; i++)
#pragma unroll
        for (int j = 0; j < 4; j++)
#pragma unroll
            for (int q = 0; q < 4; q++) c[i][j][q] = 0.f;

    for (int ck = 0; ck < 11; ck++) {
        const int KS = (ck == 10) ? 1 : 8;
        __syncthreads();
        if (ck < 8) {
#pragma unroll
            for (int it = 0; it < 16; it++) {
                const int idx = tid + it * 256;
                const int row = idx >> 5, c4 = idx & 31;
                const float4 v = *(const float4*)(attn +
                    (((size_t)(bh << 10) + l0 + row) << 10) + ck * 128 + c4 * 4);
                *(uint2*)(smc + C_AH + row * CPB + c4 * 8) =
                    make_uint2(pack_hi(v.x, v.y), pack_hi(v.z, v.w));
                *(uint2*)(smc + C_AL + row * CPB + c4 * 8) =
                    make_uint2(pack_lo(v.x, v.y), pack_lo(v.z, v.w));
            }
#pragma unroll
            for (int it = 0; it < 4; it++) {
                const int idx = tid + it * 256;
                const int row = idx >> 3, j = idx & 7;
                const size_t src = ((size_t)(bh << 10) + ck * 128 + row) * 64 + j * 8;
                *(uint4*)(smc + C_VH + row * 144 + j * 16) = *(const uint4*)((const char*)Vh + src * 2);
                *(uint4*)(smc + C_VL + row * 144 + j * 16) = *(const uint4*)((const char*)Vl + src * 2);
            }
        } else if (ck < 10) {
            const int p0 = (ck - 8) * 128;
#pragma unroll
            for (int it = 0; it < 8; it++) {
                const int idx = tid + it * 256;
                const int row = idx >> 4, j = idx & 15;
                const size_t src = ((size_t)(bh << 10) + l0 + row) * 272 + p0 + j * 8;
                *(uint4*)(smc + C_AH + row * CPB + j * 16) = *(const uint4*)((const char*)agh + src * 2);
                *(uint4*)(smc + C_AL + row * CPB + j * 16) = *(const uint4*)((const char*)agl + src * 2);
            }
#pragma unroll
            for (int it = 0; it < 32; it++) {
                const int idx = tid + it * 256;
                const int d = idx >> 7, p = idx & 127;
                const float v = relv[(size_t)(p0 + p) * 64 + d];
                __nv_bfloat16 hh = __float2bfloat16(v);
                *(__nv_bfloat16*)(smc + C_VH + (d * RVP + p) * 2) = hh;
                *(__nv_bfloat16*)(smc + C_VL + (d * RVP + p) * 2) =
                    __float2bfloat16(v - __bfloat162float(hh));
            }
        } else {
            const int row = tid >> 1, j = tid & 1;
            const size_t src = ((size_t)(bh << 10) + l0 + row) * 272 + 256 + j * 8;
            *(uint4*)(smc + C_AH + row * CPB + j * 16) = *(const uint4*)((const char*)agh + src * 2);
            *(uint4*)(smc + C_AL + row * CPB + j * 16) = *(const uint4*)((const char*)agl + src * 2);
#pragma unroll
            for (int it = 0; it < 2; it++) {
                const int idx = tid + it * 256;
                const int d = idx >> 3, jj = idx & 7;
                ((uint32_t*)(smc + C_VH))[d * (RVP / 2) + jj] = 0u;
                ((uint32_t*)(smc + C_VL))[d * (RVP / 2) + jj] = 0u;
            }
            __syncthreads();
            if (tid < 64) {
                const float v = relv[(size_t)256 * 64 + tid];
                __nv_bfloat16 hh = __float2bfloat16(v);
                *(__nv_bfloat16*)(smc + C_VH + (tid * RVP) * 2) = hh;
                *(__nv_bfloat16*)(smc + C_VL + (tid * RVP) * 2) =
                    __float2bfloat16(v - __bfloat162float(hh));
            }
        }
        __syncthreads();

        for (int kk = 0; kk < KS; kk++) {
            uint32_t a_h[2][4], a_l[2][4];
#pragma unroll
            for (int i = 0; i < 2; i++) {
                const uint32_t addr = sb + C_AH +
                    ((wm * 32 + i * 16 + (lane & 15)) * CP + kk * 16 + (lane >> 4) * 8) * 2;
                ldm4(a_h[i], addr);
                ldm4(a_l[i], addr + (C_AL - C_AH));
            }
            uint32_t b_h[2][4], b_l[2][4];
            const int mat = lane >> 3, rr8 = lane & 7;
            if (ck < 8) {
#pragma unroll
                for (int nb = 0; nb < 2; nb++) {
                    const uint32_t addr = sb + C_VH +
                        ((kk * 16 + (mat & 1) * 8 + rr8) * 72 + wn * 32 + nb * 16 + (mat >> 1) * 8) * 2;
                    ldm4t(b_h[nb], addr);
                    ldm4t(b_l[nb], addr + (C_VL - C_VH));
                }
            } else {
#pragma unroll
                for (int nb = 0; nb < 2; nb++) {
                    const uint32_t addr = sb + C_VH +
                        ((wn * 32 + nb * 16 + (mat >> 1) * 8 + rr8) * RVP + kk * 16 + (mat & 1) * 8) * 2;
                    ldm4(b_h[nb], addr);
                    ldm4(b_l[nb], addr + (C_VL - C_VH));
                }
            }
#pragma unroll
            for (int i = 0; i < 2; i++)
#pragma unroll
                for (int nb = 0; nb < 2; nb++)
#pragma unroll
                    for (int half = 0; half < 2; half++) {
                        const int j = nb * 2 + half;
                        mma16816(c[i][j], a_h[i], &b_h[nb][half * 2]);
                        mma16816(c[i][j], a_h[i], &b_l[nb][half * 2]);
                        mma16816(c[i][j], a_l[i], &b_h[nb][half * 2]);
                    }
        }
    }

    const int rr = lane >> 2, cc = (lane & 3) * 2;
#pragma unroll
    for (int i = 0; i < 2; i++)
#pragma unroll
        for (int j = 0; j < 4; j++)
#pragma unroll
            for (int half = 0; half < 2; half++) {
                const int m = l0 + wm * 32 + i * 16 + rr + half * 8;
                const int d = wn * 32 + j * 8 + cc;
                const float vx = c[i][j][half * 2 + 0];
                const float vy = c[i][j][half * 2 + 1];
                const size_t off = ((size_t)(b << 10) + m) * 1024 + h * 64 + d;
                *(uint32_t*)(oh + off) = pack_hi(vx, vy);
                *(uint32_t*)(ol + off) = pack_lo(vx, vy);
            }
}

// ---------------------------------------------------------------------------
extern "C" void kernel_launch(void* const* d_in, const int* in_sizes, int n_in,
                              void* d_out, int out_size) {
    const float* query = (const float*)d_in[0];
    const float* key_  = (const float*)d_in[1];
    const float* value = (const float*)d_in[2];
    const float* w_q   = (const float*)d_in[3];
    const float* w_k   = (const float*)d_in[4];
    const float* w_v   = (const float*)d_in[5];
    const float* w_o   = (const float*)d_in[6];
    const float* b_o   = (const float*)d_in[7];
    const float* rel_k = (const float*)d_in[8];
    const float* rel_v = (const float*)d_in[9];
    const float* decay = (const float*)d_in[10];

    float* out  = (float*)d_out;
    float* attn = out + (size_t)MTOT * DMODEL;

    __nv_bfloat16 *Ah, *Al, *Wh, *Wl, *Qh, *Ql, *Kh, *Kl, *Vh, *Vl, *rkh, *rkl, *agh, *agl;
    cudaGetSymbolAddress((void**)&Ah,   g_Ah);
    cudaGetSymbolAddress((void**)&Al,   g_Al);
    cudaGetSymbolAddress((void**)&Wh,   g_Wh);
    cudaGetSymbolAddress((void**)&Wl,   g_Wl);
    cudaGetSymbolAddress((void**)&Qh,   g_Qh);
    cudaGetSymbolAddress((void**)&Ql,   g_Ql);
    cudaGetSymbolAddress((void**)&Kh,   g_Kh);
    cudaGetSymbolAddress((void**)&Kl,   g_Kl);
    cudaGetSymbolAddress((void**)&Vh,   g_Vh);
    cudaGetSymbolAddress((void**)&Vl,   g_Vl);
    cudaGetSymbolAddress((void**)&rkh,  g_rkh);
    cudaGetSymbolAddress((void**)&rkl,  g_rkl);
    cudaGetSymbolAddress((void**)&agh,  g_agh);
    cudaGetSymbolAddress((void**)&agl,  g_agl);

    cudaFuncSetAttribute(gemm_mma<0>, cudaFuncAttributeMaxDynamicSharedMemorySize, GEMM_SMEM);
    cudaFuncSetAttribute(gemm_mma<1>, cudaFuncAttributeMaxDynamicSharedMemorySize, GEMM_SMEM);
    cudaFuncSetAttribute(attn_kernel, cudaFuncAttributeMaxDynamicSharedMemorySize, ATTN_SMEM_BYTES);
    cudaFuncSetAttribute(ctx_mma, cudaFuncAttributeMaxDynamicSharedMemorySize, CTX_SMEM);

    const int nA4 = MTOT * DMODEL / 4;
    const int nW4 = DMODEL * DMODEL / 4;
    const int nR4 = NREL * DK / 4;
    const dim3 ggemm(DMODEL / 128, MTOT / 128);

    cvt_split<<<nA4 / 256, 256>>>((const float4*)query, (uint2*)Ah, (uint2*)Al, nA4);
    cvt_split<<<nW4 / 256, 256>>>((const float4*)w_q, (uint2*)Wh, (uint2*)Wl, nW4);
    gemm_mma<0><<<ggemm, 256, GEMM_SMEM>>>(Ah, Al, Wh, Wl, nullptr, nullptr, Qh, Ql);

    cvt_split<<<nA4 / 256, 256>>>((const float4*)key_, (uint2*)Ah, (uint2*)Al, nA4);
    cvt_split<<<nW4 / 256, 256>>>((const float4*)w_k, (uint2*)Wh, (uint2*)Wl, nW4);
    gemm_mma<0><<<ggemm, 256, GEMM_SMEM>>>(Ah, Al, Wh, Wl, nullptr, nullptr, Kh, Kl);

    cvt_split<<<nA4 / 256, 256>>>((const float4*)value, (uint2*)Ah, (uint2*)Al, nA4);
    cvt_split<<<nW4 / 256, 256>>>((const float4*)w_v, (uint2*)Wh, (uint2*)Wl, nW4);
    gemm_mma<0><<<ggemm, 256, GEMM_SMEM>>>(Ah, Al, Wh, Wl, nullptr, nullptr, Vh, Vl);

    cvt_split<<<(nR4 + 255) / 256, 256>>>((const float4*)rel_k, (uint2*)rkh, (uint2*)rkl, nR4);

    attn_kernel<<<dim3(SEQ / 16, BH), 256, ATTN_SMEM_BYTES>>>(Qh, Ql, Kh, Kl, rkh, rkl,
                                                              decay, attn, agh, agl);

    // ctx writes bf16 hi/lo directly into Ah/Al (row-major [MTOT][DMODEL])
    ctx_mma<<<dim3(SEQ / 128, BH), 256, CTX_SMEM>>>(attn, Vh, Vl, agh, agl, rel_v, Ah, Al);

    cvt_split<<<nW4 / 256, 256>>>((const float4*)w_o, (uint2*)Wh, (uint2*)Wl, nW4);
    gemm_mma<1><<<ggemm, 256, GEMM_SMEM>>>(Ah, Al, Wh, Wl, b_o, out, nullptr, nullptr);
}